// round 1
// baseline (speedup 1.0000x reference)
#include <cuda_runtime.h>
#include <math.h>

// Problem constants
#define B_   64
#define S_   196
#define E_   768
#define H_   4
#define HD_  192
#define M_   (B_*S_)        // 12544
#define NE_  (B_*S_*E_)     // 9,633,792
#define NS_  (B_*H_*S_*S_)  // 9,834,496
#define LN_N (S_*E_)        // 150,528
#define LN_CHUNKS 8
#define LN_CH (LN_N/LN_CHUNKS) // 18816

// ---------------- scratch (device globals; no allocation allowed) ----------
__device__ float g_emb[NE_];
__device__ float g_h[NE_];
__device__ float g_q[NE_];
__device__ float g_k[NE_];
__device__ float g_v[NE_];
__device__ float g_o[NE_];
__device__ float g_op[NE_];
__device__ float g_attn[NS_];
__device__ float g_psum[B_*LN_CHUNKS];
__device__ float g_psq[B_*LN_CHUNKS];
__device__ float g_mu[B_];
__device__ float g_rstd[B_];

// ============================================================================
// Patch-embed GEMM:  emb[m, n] = sum_k patches[m,k] * conv_w[n,k] + conv_b[n]
// patches gathered on the fly from x[B,3,224,224].
// M=12544 (exact 98*128), N=768 (exact 6*128), K=768 (exact 48*16).
// ============================================================================
__global__ __launch_bounds__(256) void patch_embed_gemm(
    const float* __restrict__ x, const float* __restrict__ W,
    const float* __restrict__ bias, float* __restrict__ C)
{
    __shared__ float As[16][129];
    __shared__ float Bs[16][129];
    const int tid = threadIdx.x;
    const int m0 = blockIdx.y * 128;
    const int n0 = blockIdx.x * 128;
    const int ty = tid >> 4, tx = tid & 15;

    // Precompute per-thread row bases (rows fixed across K loop)
    const float* arow[2];
    const float* brow[2];
#pragma unroll
    for (int i = 0; i < 2; i++) {
        int idx = tid + i * 256;
        int row = idx >> 2;
        int m = m0 + row;
        int b = m / S_;
        int s = m - b * S_;
        int gy = s / 14, gx = s - gy * 14;
        // base of this patch in x: x[b, 0, gy*16, gx*16]
        arow[i] = x + (((size_t)(b * 3) * 224 + gy * 16) * 224 + gx * 16);
        brow[i] = W + (size_t)(n0 + row) * E_;
    }

    float acc[8][8] = {};
    for (int k0 = 0; k0 < E_; k0 += 16) {
#pragma unroll
        for (int i = 0; i < 2; i++) {
            int idx = tid + i * 256;
            int row = idx >> 2;
            int kq = (idx & 3) << 2;
            int k = k0 + kq;
            int c  = k >> 8;            // channel
            int py = (k & 255) >> 4;    // row in patch
            int px = k & 15;            // col in patch (multiple of 4)
            float4 va = *(const float4*)(arow[i] + ((size_t)c * 224 * 224) + (size_t)py * 224 + px);
            As[kq+0][row] = va.x; As[kq+1][row] = va.y;
            As[kq+2][row] = va.z; As[kq+3][row] = va.w;
            float4 vb = *(const float4*)(brow[i] + k0 + kq);
            Bs[kq+0][row] = vb.x; Bs[kq+1][row] = vb.y;
            Bs[kq+2][row] = vb.z; Bs[kq+3][row] = vb.w;
        }
        __syncthreads();
#pragma unroll
        for (int kk = 0; kk < 16; kk++) {
            float ra[8], rb[8];
#pragma unroll
            for (int i = 0; i < 8; i++) ra[i] = As[kk][ty * 8 + i];
#pragma unroll
            for (int j = 0; j < 8; j++) rb[j] = Bs[kk][tx * 8 + j];
#pragma unroll
            for (int i = 0; i < 8; i++)
#pragma unroll
                for (int j = 0; j < 8; j++)
                    acc[i][j] = fmaf(ra[i], rb[j], acc[i][j]);
        }
        __syncthreads();
    }
#pragma unroll
    for (int i = 0; i < 8; i++) {
        int m = m0 + ty * 8 + i;
#pragma unroll
        for (int j = 0; j < 8; j += 4) {
            int n = n0 + tx * 8 + j;
            float4 v;
            v.x = acc[i][j+0] + bias[n+0];
            v.y = acc[i][j+1] + bias[n+1];
            v.z = acc[i][j+2] + bias[n+2];
            v.w = acc[i][j+3] + bias[n+3];
            *(float4*)(C + (size_t)m * E_ + n) = v;
        }
    }
}

// ============================================================================
// Generic GEMM: C[m,n] = sum_k A[m,k] * W[n,k] + bias[n]
// A: [M,K] row-major, W: [N,K] row-major (torch Linear). M=12544,N=K=768.
// ============================================================================
__global__ __launch_bounds__(256) void gemm768(
    const float* __restrict__ A, const float* __restrict__ W,
    const float* __restrict__ bias, float* __restrict__ C)
{
    __shared__ float As[16][129];
    __shared__ float Bs[16][129];
    const int tid = threadIdx.x;
    const int m0 = blockIdx.y * 128;
    const int n0 = blockIdx.x * 128;
    const int ty = tid >> 4, tx = tid & 15;

    const float* arow[2];
    const float* brow[2];
#pragma unroll
    for (int i = 0; i < 2; i++) {
        int idx = tid + i * 256;
        int row = idx >> 2;
        arow[i] = A + (size_t)(m0 + row) * E_;
        brow[i] = W + (size_t)(n0 + row) * E_;
    }

    float acc[8][8] = {};
    for (int k0 = 0; k0 < E_; k0 += 16) {
#pragma unroll
        for (int i = 0; i < 2; i++) {
            int idx = tid + i * 256;
            int row = idx >> 2;
            int kq = (idx & 3) << 2;
            float4 va = *(const float4*)(arow[i] + k0 + kq);
            As[kq+0][row] = va.x; As[kq+1][row] = va.y;
            As[kq+2][row] = va.z; As[kq+3][row] = va.w;
            float4 vb = *(const float4*)(brow[i] + k0 + kq);
            Bs[kq+0][row] = vb.x; Bs[kq+1][row] = vb.y;
            Bs[kq+2][row] = vb.z; Bs[kq+3][row] = vb.w;
        }
        __syncthreads();
#pragma unroll
        for (int kk = 0; kk < 16; kk++) {
            float ra[8], rb[8];
#pragma unroll
            for (int i = 0; i < 8; i++) ra[i] = As[kk][ty * 8 + i];
#pragma unroll
            for (int j = 0; j < 8; j++) rb[j] = Bs[kk][tx * 8 + j];
#pragma unroll
            for (int i = 0; i < 8; i++)
#pragma unroll
                for (int j = 0; j < 8; j++)
                    acc[i][j] = fmaf(ra[i], rb[j], acc[i][j]);
        }
        __syncthreads();
    }
#pragma unroll
    for (int i = 0; i < 8; i++) {
        int m = m0 + ty * 8 + i;
#pragma unroll
        for (int j = 0; j < 8; j += 4) {
            int n = n0 + tx * 8 + j;
            float4 v;
            v.x = acc[i][j+0] + bias[n+0];
            v.y = acc[i][j+1] + bias[n+1];
            v.z = acc[i][j+2] + bias[n+2];
            v.w = acc[i][j+3] + bias[n+3];
            *(float4*)(C + (size_t)m * E_ + n) = v;
        }
    }
}

// ============================================================================
// Attention scores: g_attn[bh,i,j] = scale * sum_d q[b,i,h*HD+d]*k[b,j,h*HD+d]
// Per (b,h): M=N=196, K=192. 64x64 tiles, 4x4 per thread.
// ============================================================================
__global__ __launch_bounds__(256) void attn_scores(
    const float* __restrict__ q, const float* __restrict__ k)
{
    const int bh = blockIdx.z;
    const int b = bh >> 2, h = bh & 3;
    const float* Ap = q + (size_t)b * S_ * E_ + h * HD_;
    const float* Bp = k + (size_t)b * S_ * E_ + h * HD_;
    float* Cp = g_attn + (size_t)bh * S_ * S_;
    __shared__ float As[16][65];
    __shared__ float Bs[16][65];
    const int tid = threadIdx.x;
    const int m0 = blockIdx.y * 64, n0 = blockIdx.x * 64;
    const int ty = tid >> 4, tx = tid & 15;
    float acc[4][4] = {};
    const int row = tid >> 2, kq = (tid & 3) << 2;
    const int m = m0 + row, n = n0 + row;

    for (int k0 = 0; k0 < HD_; k0 += 16) {
        float4 va = (m < S_) ? *(const float4*)(Ap + (size_t)m * E_ + k0 + kq)
                             : make_float4(0.f, 0.f, 0.f, 0.f);
        float4 vb = (n < S_) ? *(const float4*)(Bp + (size_t)n * E_ + k0 + kq)
                             : make_float4(0.f, 0.f, 0.f, 0.f);
        As[kq+0][row] = va.x; As[kq+1][row] = va.y;
        As[kq+2][row] = va.z; As[kq+3][row] = va.w;
        Bs[kq+0][row] = vb.x; Bs[kq+1][row] = vb.y;
        Bs[kq+2][row] = vb.z; Bs[kq+3][row] = vb.w;
        __syncthreads();
#pragma unroll
        for (int kk = 0; kk < 16; kk++) {
            float ra[4], rb[4];
#pragma unroll
            for (int i = 0; i < 4; i++) ra[i] = As[kk][ty * 4 + i];
#pragma unroll
            for (int j = 0; j < 4; j++) rb[j] = Bs[kk][tx * 4 + j];
#pragma unroll
            for (int i = 0; i < 4; i++)
#pragma unroll
                for (int j = 0; j < 4; j++)
                    acc[i][j] = fmaf(ra[i], rb[j], acc[i][j]);
        }
        __syncthreads();
    }
    const float scale = rsqrtf((float)HD_);
#pragma unroll
    for (int i = 0; i < 4; i++) {
        int mi = m0 + ty * 4 + i;
        if (mi >= S_) continue;
#pragma unroll
        for (int j = 0; j < 4; j++) {
            int nj = n0 + tx * 4 + j;
            if (nj < S_) Cp[(size_t)mi * S_ + nj] = acc[i][j] * scale;
        }
    }
}

// ============================================================================
// Row softmax over g_attn: one warp per row of 196.
// ============================================================================
__global__ __launch_bounds__(256) void softmax_rows()
{
    const int warp = (blockIdx.x * blockDim.x + threadIdx.x) >> 5;
    const int lane = threadIdx.x & 31;
    if (warp >= B_ * H_ * S_) return;
    float* p = g_attn + (size_t)warp * S_;
    float v[7];
    float mx = -1e30f;
#pragma unroll
    for (int i = 0; i < 7; i++) {
        int j = lane + i * 32;
        v[i] = (j < S_) ? p[j] : -1e30f;
        mx = fmaxf(mx, v[i]);
    }
#pragma unroll
    for (int o = 16; o > 0; o >>= 1) mx = fmaxf(mx, __shfl_xor_sync(0xFFFFFFFFu, mx, o));
    float sum = 0.f;
#pragma unroll
    for (int i = 0; i < 7; i++) {
        int j = lane + i * 32;
        v[i] = (j < S_) ? __expf(v[i] - mx) : 0.f;
        sum += v[i];
    }
#pragma unroll
    for (int o = 16; o > 0; o >>= 1) sum += __shfl_xor_sync(0xFFFFFFFFu, sum, o);
    const float inv = 1.0f / sum;
#pragma unroll
    for (int i = 0; i < 7; i++) {
        int j = lane + i * 32;
        if (j < S_) p[j] = v[i] * inv;
    }
}

// ============================================================================
// AV: g_o[b,i,h*HD+n] = sum_j attn[bh,i,j] * v[b,j,h*HD+n]
// Per (b,h): M=196, N=192, K=196. 64x64 tiles.
// ============================================================================
__global__ __launch_bounds__(256) void attn_av(const float* __restrict__ v)
{
    const int bh = blockIdx.z;
    const int b = bh >> 2, h = bh & 3;
    const float* Ap = g_attn + (size_t)bh * S_ * S_;
    const float* Bp = v + (size_t)b * S_ * E_ + h * HD_;
    float* Cp = g_o + (size_t)b * S_ * E_ + h * HD_;
    __shared__ float As[16][65];
    __shared__ float Bs[16][65];
    const int tid = threadIdx.x;
    const int m0 = blockIdx.y * 64, n0 = blockIdx.x * 64;
    const int ty = tid >> 4, tx = tid & 15;
    float acc[4][4] = {};
    const int arow = tid >> 2, akq = (tid & 3) << 2;
    const int am = m0 + arow;
    const int brow = tid >> 4;            // k-row within tile
    const int bnq = (tid & 15) << 2;      // n within tile

    for (int k0 = 0; k0 < S_; k0 += 16) {
        int ak = k0 + akq;
        float4 va = (am < S_ && ak < S_) ? *(const float4*)(Ap + (size_t)am * S_ + ak)
                                         : make_float4(0.f, 0.f, 0.f, 0.f);
        As[akq+0][arow] = va.x; As[akq+1][arow] = va.y;
        As[akq+2][arow] = va.z; As[akq+3][arow] = va.w;
        int krow = k0 + brow;
        float4 vb = (krow < S_) ? *(const float4*)(Bp + (size_t)krow * E_ + n0 + bnq)
                                : make_float4(0.f, 0.f, 0.f, 0.f);
        Bs[brow][bnq+0] = vb.x; Bs[brow][bnq+1] = vb.y;
        Bs[brow][bnq+2] = vb.z; Bs[brow][bnq+3] = vb.w;
        __syncthreads();
#pragma unroll
        for (int kk = 0; kk < 16; kk++) {
            float ra[4], rb[4];
#pragma unroll
            for (int i = 0; i < 4; i++) ra[i] = As[kk][ty * 4 + i];
#pragma unroll
            for (int j = 0; j < 4; j++) rb[j] = Bs[kk][tx * 4 + j];
#pragma unroll
            for (int i = 0; i < 4; i++)
#pragma unroll
                for (int j = 0; j < 4; j++)
                    acc[i][j] = fmaf(ra[i], rb[j], acc[i][j]);
        }
        __syncthreads();
    }
#pragma unroll
    for (int i = 0; i < 4; i++) {
        int mi = m0 + ty * 4 + i;
        if (mi >= S_) continue;
#pragma unroll
        for (int j = 0; j < 4; j++) {
            int nj = n0 + tx * 4 + j;
            Cp[(size_t)mi * E_ + nj] = acc[i][j];
        }
    }
}

// ============================================================================
// LayerNorm over [S,E] per batch: partial -> finalize -> apply
// ============================================================================
__global__ __launch_bounds__(256) void ln_partial(
    const float* __restrict__ A, const float* __restrict__ R)
{
    const int b = blockIdx.x, chunk = blockIdx.y;
    const size_t base = (size_t)b * LN_N + (size_t)chunk * LN_CH;
    float s = 0.f, sq = 0.f;
    for (int i = threadIdx.x; i < LN_CH; i += 256) {
        float v = A[base + i];
        if (R) v += R[base + i];
        s += v; sq += v * v;
    }
    __shared__ float ss[256], sb[256];
    ss[threadIdx.x] = s; sb[threadIdx.x] = sq;
    __syncthreads();
    for (int o = 128; o > 0; o >>= 1) {
        if (threadIdx.x < o) {
            ss[threadIdx.x] += ss[threadIdx.x + o];
            sb[threadIdx.x] += sb[threadIdx.x + o];
        }
        __syncthreads();
    }
    if (threadIdx.x == 0) {
        g_psum[b * LN_CHUNKS + chunk] = ss[0];
        g_psq [b * LN_CHUNKS + chunk] = sb[0];
    }
}

__global__ void ln_finalize()
{
    const int b = threadIdx.x;
    if (b >= B_) return;
    float s = 0.f, sq = 0.f;
#pragma unroll
    for (int i = 0; i < LN_CHUNKS; i++) {
        s  += g_psum[b * LN_CHUNKS + i];
        sq += g_psq [b * LN_CHUNKS + i];
    }
    const float inv_n = 1.0f / (float)LN_N;
    float mu = s * inv_n;
    float var = sq * inv_n - mu * mu;
    g_mu[b] = mu;
    g_rstd[b] = rsqrtf(var + 1e-5f);
}

__global__ __launch_bounds__(256) void ln_apply(
    const float* __restrict__ A, const float* __restrict__ R,
    const float* __restrict__ w, const float* __restrict__ bias,
    float* __restrict__ out)
{
    const int gid = blockIdx.x * 256 + threadIdx.x;
    if (gid >= NE_) return;
    const int b = gid / LN_N;
    const int r = gid - b * LN_N;
    float v = A[gid];
    if (R) v += R[gid];
    out[gid] = (v - g_mu[b]) * g_rstd[b] * w[r] + bias[r];
}

// ============================================================================
// Launch
// ============================================================================
extern "C" void kernel_launch(void* const* d_in, const int* in_sizes, int n_in,
                              void* d_out, int out_size)
{
    const float* x      = (const float*)d_in[0];
    const float* conv_w = (const float*)d_in[1];
    const float* conv_b = (const float*)d_in[2];
    const float* wq = (const float*)d_in[3];  const float* bq = (const float*)d_in[4];
    const float* wk = (const float*)d_in[5];  const float* bk = (const float*)d_in[6];
    const float* wv = (const float*)d_in[7];  const float* bv = (const float*)d_in[8];
    const float* wo = (const float*)d_in[9];  const float* bo = (const float*)d_in[10];
    const float* ln1w = (const float*)d_in[11]; const float* ln1b = (const float*)d_in[12];
    const float* ln2w = (const float*)d_in[13]; const float* ln2b = (const float*)d_in[14];
    float* out = (float*)d_out;

    float *emb, *h, *q, *k, *v, *o, *op;
    cudaGetSymbolAddress((void**)&emb, g_emb);
    cudaGetSymbolAddress((void**)&h,   g_h);
    cudaGetSymbolAddress((void**)&q,   g_q);
    cudaGetSymbolAddress((void**)&k,   g_k);
    cudaGetSymbolAddress((void**)&v,   g_v);
    cudaGetSymbolAddress((void**)&o,   g_o);
    cudaGetSymbolAddress((void**)&op,  g_op);

    const dim3 gemm_grid(E_ / 128, M_ / 128);      // (6, 98)
    const dim3 sc_grid(4, 4, B_ * H_);             // 64x64 tiles over 196x196
    const dim3 av_grid(3, 4, B_ * H_);             // N=192 -> 3 tiles
    const dim3 lnp_grid(B_, LN_CHUNKS);
    const int  lna_blocks = NE_ / 256;             // 37632 exact
    const int  sm_blocks = (B_ * H_ * S_ * 32 + 255) / 256; // warp per row

    // 1. patch embedding
    patch_embed_gemm<<<gemm_grid, 256>>>(x, conv_w, conv_b, emb);
    // 2. LN1
    ln_partial<<<lnp_grid, 256>>>(emb, nullptr);
    ln_finalize<<<1, 64>>>();
    ln_apply<<<lna_blocks, 256>>>(emb, nullptr, ln1w, ln1b, h);
    // 3. QKV
    gemm768<<<gemm_grid, 256>>>(h, wq, bq, q);
    gemm768<<<gemm_grid, 256>>>(h, wk, bk, k);
    gemm768<<<gemm_grid, 256>>>(h, wv, bv, v);
    // 4. attention
    attn_scores<<<sc_grid, 256>>>(q, k);
    softmax_rows<<<sm_blocks, 256>>>();
    attn_av<<<av_grid, 256>>>(v);
    // 5. output projection
    gemm768<<<gemm_grid, 256>>>(o, wo, bo, op);
    // 6. residual + LN2 -> out
    ln_partial<<<lnp_grid, 256>>>(emb, op);
    ln_finalize<<<1, 64>>>();
    ln_apply<<<lna_blocks, 256>>>(emb, op, ln2w, ln2b, out);
}

// round 3
// speedup vs baseline: 1.6014x; 1.6014x over previous
#include <cuda_runtime.h>
#include <cuda_bf16.h>
#include <math.h>
#include <stdint.h>

// Problem constants
#define B_   64
#define S_   196
#define E_   768
#define H_   4
#define HD_  192
#define M_   (B_*S_)        // 12544
#define NE_  (B_*S_*E_)     // 9,633,792
#define NS_  (B_*H_*S_*S_)  // 9,834,496
#define LN_N (S_*E_)        // 150,528
#define LN_CHUNKS 8
#define LN_CH (LN_N/LN_CHUNKS)
#define WN_  (E_*E_)        // 589824 weight elems

// ---------------- scratch (device globals; no allocation allowed) ----------
__device__ __align__(256) float g_emb[NE_];
__device__ __align__(256) float g_q[NE_];
__device__ __align__(256) float g_k[NE_];
__device__ __align__(256) float g_v[NE_];
__device__ __align__(256) float g_op[NE_];
__device__ __align__(256) float g_attn[NS_];
__device__ float g_psum[B_*LN_CHUNKS];
__device__ float g_psq[B_*LN_CHUNKS];
__device__ float g_mu[B_];
__device__ float g_rstd[B_];

// bf16 hi/lo split buffers
__device__ __align__(256) __nv_bfloat16 g_ap_hi[NE_];   // patches
__device__ __align__(256) __nv_bfloat16 g_ap_lo[NE_];
__device__ __align__(256) __nv_bfloat16 g_h_hi[NE_];    // LN1 output
__device__ __align__(256) __nv_bfloat16 g_h_lo[NE_];
__device__ __align__(256) __nv_bfloat16 g_o_hi[NE_];    // attention output
__device__ __align__(256) __nv_bfloat16 g_o_lo[NE_];
__device__ __align__(256) __nv_bfloat16 g_w_hi[5][WN_]; // conv_w, wq, wk, wv, wo
__device__ __align__(256) __nv_bfloat16 g_w_lo[5][WN_];

// ============================================================================
// PTX helpers (mma.sync / ldmatrix — supported on base sm_103 target)
// ============================================================================
__device__ __forceinline__ uint32_t smem_u32(const void* p) {
    uint32_t a;
    asm("{ .reg .u64 t; cvta.to.shared.u64 t, %1; cvt.u32.u64 %0, t; }"
        : "=r"(a) : "l"(p));
    return a;
}
__device__ __forceinline__ void ldsm_x4(uint32_t* r, uint32_t addr) {
    asm volatile("ldmatrix.sync.aligned.m8n8.x4.shared.b16 {%0,%1,%2,%3}, [%4];"
                 : "=r"(r[0]), "=r"(r[1]), "=r"(r[2]), "=r"(r[3]) : "r"(addr));
}
__device__ __forceinline__ void ldsm_x2(uint32_t* r, uint32_t addr) {
    asm volatile("ldmatrix.sync.aligned.m8n8.x2.shared.b16 {%0,%1}, [%2];"
                 : "=r"(r[0]), "=r"(r[1]) : "r"(addr));
}
__device__ __forceinline__ void mma16816(float* c, const uint32_t* a, const uint32_t* b) {
    asm volatile(
        "mma.sync.aligned.m16n8k16.row.col.f32.bf16.bf16.f32 "
        "{%0,%1,%2,%3}, {%4,%5,%6,%7}, {%8,%9}, {%0,%1,%2,%3};"
        : "+f"(c[0]), "+f"(c[1]), "+f"(c[2]), "+f"(c[3])
        : "r"(a[0]), "r"(a[1]), "r"(a[2]), "r"(a[3]), "r"(b[0]), "r"(b[1]));
}

// ============================================================================
// HMMA bf16-split GEMM:
//   C[m,n] = sum_k A[m,k]*B[n,k] + bias[n],  A*B ~= Ahi*Bhi + Alo*Bhi + Ahi*Blo
// M=12544, N=768, K=768. CTA tile 128x128, K-stage 32, 72 stages (3 passes x 24).
// 8 warps: warp tile 64x32 (4x4 mma m16n8k16 grid).
// ============================================================================
#define BK 32
#define KPAD 8
#define ASTR (BK + KPAD)          // 40 bf16 per row => 80B stride (conflict-free ldsm)
#define STAGE_BYTES (128 * ASTR * 2)

__global__ __launch_bounds__(256) void gemm_mma(
    const __nv_bfloat16* __restrict__ Ahi, const __nv_bfloat16* __restrict__ Alo,
    const __nv_bfloat16* __restrict__ Bhi, const __nv_bfloat16* __restrict__ Blo,
    const float* __restrict__ bias, float* __restrict__ C)
{
    __shared__ __nv_bfloat16 As[2][128][ASTR];
    __shared__ __nv_bfloat16 Bs[2][128][ASTR];
    const int tid = threadIdx.x;
    const int wid = tid >> 5, lane = tid & 31;
    const int m0 = blockIdx.y * 128, n0 = blockIdx.x * 128;
    const int wm = (wid >> 2) * 64;     // 0 or 64
    const int wn = (wid & 3) * 32;      // 0..96

    // loader mapping: thread t -> row t/2 (0..127), 16 bf16 at col (t&1)*16
    const int lrow = tid >> 1;
    const int lcol = (tid & 1) * 16;

    float acc[4][4][4];
#pragma unroll
    for (int i = 0; i < 4; i++)
#pragma unroll
        for (int j = 0; j < 4; j++)
#pragma unroll
            for (int q = 0; q < 4; q++) acc[i][j][q] = 0.f;

    uint4 ra0, ra1, rb0, rb1;
    auto gload = [&](int c) {
        const int seg = c / 24;
        const int k0 = (c - seg * 24) * 32 + lcol;
        const __nv_bfloat16* A = (seg == 1) ? Alo : Ahi;
        const __nv_bfloat16* B = (seg == 2) ? Blo : Bhi;
        const __nv_bfloat16* ap = A + (size_t)(m0 + lrow) * E_ + k0;
        const __nv_bfloat16* bp = B + (size_t)(n0 + lrow) * E_ + k0;
        ra0 = *(const uint4*)ap; ra1 = *(const uint4*)(ap + 8);
        rb0 = *(const uint4*)bp; rb1 = *(const uint4*)(bp + 8);
    };
    auto sstore = [&](int st) {
        *(uint4*)&As[st][lrow][lcol]     = ra0;
        *(uint4*)&As[st][lrow][lcol + 8] = ra1;
        *(uint4*)&Bs[st][lrow][lcol]     = rb0;
        *(uint4*)&Bs[st][lrow][lcol + 8] = rb1;
    };

    const uint32_t aBase = smem_u32(&As[0][0][0]);
    const uint32_t bBase = smem_u32(&Bs[0][0][0]);
    // ldmatrix lane addressing
    const int arow = wm + (lane & 15);
    const int akoff = (lane >> 4) * 8;
    const int brow = wn + (lane & 7);
    const int bkoff = ((lane >> 3) & 1) * 8;

    gload(0);
    sstore(0);
    __syncthreads();

    for (int c = 0; c < 72; c++) {
        const int st = c & 1;
        if (c + 1 < 72) gload(c + 1);   // overlap gmem latency with compute
        const uint32_t aStage = aBase + st * STAGE_BYTES;
        const uint32_t bStage = bBase + st * STAGE_BYTES;
#pragma unroll
        for (int ks = 0; ks < 2; ks++) {
            const int k = ks * 16;
            uint32_t af[4][4], bf[4][2];
#pragma unroll
            for (int mt = 0; mt < 4; mt++)
                ldsm_x4(af[mt], aStage + ((arow + mt * 16) * ASTR + k + akoff) * 2);
#pragma unroll
            for (int nt = 0; nt < 4; nt++)
                ldsm_x2(bf[nt], bStage + ((brow + nt * 8) * ASTR + k + bkoff) * 2);
#pragma unroll
            for (int mt = 0; mt < 4; mt++)
#pragma unroll
                for (int nt = 0; nt < 4; nt++)
                    mma16816(acc[mt][nt], af[mt], bf[nt]);
        }
        // stage st^1 was fully consumed in iteration c-1; safe to overwrite now
        if (c + 1 < 72) sstore(st ^ 1);
        __syncthreads();
    }

    // Epilogue: C fragment: c0,c1 -> (row=lane/4, col=2*(lane%4)+{0,1}); c2,c3 -> row+8
    const int erow = lane >> 2;
    const int ecol = (lane & 3) * 2;
#pragma unroll
    for (int mt = 0; mt < 4; mt++) {
#pragma unroll
        for (int nt = 0; nt < 4; nt++) {
            const int col = n0 + wn + nt * 8 + ecol;
            const float b0 = bias[col], b1 = bias[col + 1];
            const int r0 = m0 + wm + mt * 16 + erow;
            float2 v0 = make_float2(acc[mt][nt][0] + b0, acc[mt][nt][1] + b1);
            float2 v1 = make_float2(acc[mt][nt][2] + b0, acc[mt][nt][3] + b1);
            *(float2*)&C[(size_t)r0 * E_ + col] = v0;
            *(float2*)&C[(size_t)(r0 + 8) * E_ + col] = v1;
        }
    }
}

// ============================================================================
// Split conversions
// ============================================================================
__device__ __forceinline__ void split1(float x, __nv_bfloat16& hi, __nv_bfloat16& lo) {
    hi = __float2bfloat16(x);
    lo = __float2bfloat16(x - __bfloat162float(hi));
}

__global__ __launch_bounds__(256) void weight_split(
    const float* __restrict__ w, __nv_bfloat16* __restrict__ hi,
    __nv_bfloat16* __restrict__ lo)
{
    const int gid = blockIdx.x * 256 + threadIdx.x;
    if (gid >= WN_ / 4) return;
    float4 v = *(const float4*)(w + gid * 4);
    __nv_bfloat16 h0, l0;
#pragma unroll
    for (int i = 0; i < 4; i++) {
        split1((&v.x)[i], h0, l0);
        hi[gid * 4 + i] = h0;
        lo[gid * 4 + i] = l0;
    }
}

// patch extraction + split: Ap[m,k] from x[B,3,224,224]
__global__ __launch_bounds__(256) void patch_split(
    const float* __restrict__ x, __nv_bfloat16* __restrict__ hi,
    __nv_bfloat16* __restrict__ lo)
{
    const int gid = blockIdx.x * 256 + threadIdx.x;
    if (gid >= NE_ / 4) return;
    const int m = gid / 192;
    const int k = (gid - m * 192) * 4;
    const int b = m / S_;
    const int s = m - b * S_;
    const int gy = s / 14, gx = s - gy * 14;
    const int c = k >> 8;
    const int py = (k >> 4) & 15;
    const int px = k & 15;
    const float* src = x + ((((size_t)b * 3 + c) * 224 + gy * 16 + py) * 224 + gx * 16 + px);
    float4 v = *(const float4*)src;
    const size_t o = (size_t)m * E_ + k;
    __nv_bfloat16 h0, l0;
#pragma unroll
    for (int i = 0; i < 4; i++) {
        split1((&v.x)[i], h0, l0);
        hi[o + i] = h0;
        lo[o + i] = l0;
    }
}

// ============================================================================
// Attention (fp32): scores, softmax, AV (AV writes bf16 hi/lo)
// ============================================================================
__global__ __launch_bounds__(256) void attn_scores(
    const float* __restrict__ q, const float* __restrict__ k)
{
    const int bh = blockIdx.z;
    const int b = bh >> 2, h = bh & 3;
    const float* Ap = q + (size_t)b * S_ * E_ + h * HD_;
    const float* Bp = k + (size_t)b * S_ * E_ + h * HD_;
    float* Cp = g_attn + (size_t)bh * S_ * S_;
    __shared__ float As[16][65];
    __shared__ float Bs[16][65];
    const int tid = threadIdx.x;
    const int m0 = blockIdx.y * 64, n0 = blockIdx.x * 64;
    const int ty = tid >> 4, tx = tid & 15;
    float acc[4][4] = {};
    const int row = tid >> 2, kq = (tid & 3) << 2;
    const int m = m0 + row, n = n0 + row;

    for (int k0 = 0; k0 < HD_; k0 += 16) {
        float4 va = (m < S_) ? *(const float4*)(Ap + (size_t)m * E_ + k0 + kq)
                             : make_float4(0.f, 0.f, 0.f, 0.f);
        float4 vb = (n < S_) ? *(const float4*)(Bp + (size_t)n * E_ + k0 + kq)
                             : make_float4(0.f, 0.f, 0.f, 0.f);
        As[kq+0][row] = va.x; As[kq+1][row] = va.y;
        As[kq+2][row] = va.z; As[kq+3][row] = va.w;
        Bs[kq+0][row] = vb.x; Bs[kq+1][row] = vb.y;
        Bs[kq+2][row] = vb.z; Bs[kq+3][row] = vb.w;
        __syncthreads();
#pragma unroll
        for (int kk = 0; kk < 16; kk++) {
            float ra[4], rb[4];
#pragma unroll
            for (int i = 0; i < 4; i++) ra[i] = As[kk][ty * 4 + i];
#pragma unroll
            for (int j = 0; j < 4; j++) rb[j] = Bs[kk][tx * 4 + j];
#pragma unroll
            for (int i = 0; i < 4; i++)
#pragma unroll
                for (int j = 0; j < 4; j++)
                    acc[i][j] = fmaf(ra[i], rb[j], acc[i][j]);
        }
        __syncthreads();
    }
    const float scale = rsqrtf((float)HD_);
#pragma unroll
    for (int i = 0; i < 4; i++) {
        int mi = m0 + ty * 4 + i;
        if (mi >= S_) continue;
#pragma unroll
        for (int j = 0; j < 4; j++) {
            int nj = n0 + tx * 4 + j;
            if (nj < S_) Cp[(size_t)mi * S_ + nj] = acc[i][j] * scale;
        }
    }
}

__global__ __launch_bounds__(256) void softmax_rows()
{
    const int warp = (blockIdx.x * blockDim.x + threadIdx.x) >> 5;
    const int lane = threadIdx.x & 31;
    if (warp >= B_ * H_ * S_) return;
    float* p = g_attn + (size_t)warp * S_;
    float v[7];
    float mx = -1e30f;
#pragma unroll
    for (int i = 0; i < 7; i++) {
        int j = lane + i * 32;
        v[i] = (j < S_) ? p[j] : -1e30f;
        mx = fmaxf(mx, v[i]);
    }
#pragma unroll
    for (int o = 16; o > 0; o >>= 1) mx = fmaxf(mx, __shfl_xor_sync(0xFFFFFFFFu, mx, o));
    float sum = 0.f;
#pragma unroll
    for (int i = 0; i < 7; i++) {
        int j = lane + i * 32;
        v[i] = (j < S_) ? __expf(v[i] - mx) : 0.f;
        sum += v[i];
    }
#pragma unroll
    for (int o = 16; o > 0; o >>= 1) sum += __shfl_xor_sync(0xFFFFFFFFu, sum, o);
    const float inv = 1.0f / sum;
#pragma unroll
    for (int i = 0; i < 7; i++) {
        int j = lane + i * 32;
        if (j < S_) p[j] = v[i] * inv;
    }
}

__global__ __launch_bounds__(256) void attn_av(const float* __restrict__ v)
{
    const int bh = blockIdx.z;
    const int b = bh >> 2, h = bh & 3;
    const float* Ap = g_attn + (size_t)bh * S_ * S_;
    const float* Bp = v + (size_t)b * S_ * E_ + h * HD_;
    __shared__ float As[16][65];
    __shared__ float Bs[16][65];
    const int tid = threadIdx.x;
    const int m0 = blockIdx.y * 64, n0 = blockIdx.x * 64;
    const int ty = tid >> 4, tx = tid & 15;
    float acc[4][4] = {};
    const int arow = tid >> 2, akq = (tid & 3) << 2;
    const int am = m0 + arow;
    const int brow = tid >> 4;
    const int bnq = (tid & 15) << 2;

    for (int k0 = 0; k0 < S_; k0 += 16) {
        int ak = k0 + akq;
        float4 va = (am < S_ && ak < S_) ? *(const float4*)(Ap + (size_t)am * S_ + ak)
                                         : make_float4(0.f, 0.f, 0.f, 0.f);
        As[akq+0][arow] = va.x; As[akq+1][arow] = va.y;
        As[akq+2][arow] = va.z; As[akq+3][arow] = va.w;
        int krow = k0 + brow;
        float4 vb = (krow < S_) ? *(const float4*)(Bp + (size_t)krow * E_ + n0 + bnq)
                                : make_float4(0.f, 0.f, 0.f, 0.f);
        Bs[brow][bnq+0] = vb.x; Bs[brow][bnq+1] = vb.y;
        Bs[brow][bnq+2] = vb.z; Bs[brow][bnq+3] = vb.w;
        __syncthreads();
#pragma unroll
        for (int kk = 0; kk < 16; kk++) {
            float ra[4], rb[4];
#pragma unroll
            for (int i = 0; i < 4; i++) ra[i] = As[kk][ty * 4 + i];
#pragma unroll
            for (int j = 0; j < 4; j++) rb[j] = Bs[kk][tx * 4 + j];
#pragma unroll
            for (int i = 0; i < 4; i++)
#pragma unroll
                for (int j = 0; j < 4; j++)
                    acc[i][j] = fmaf(ra[i], rb[j], acc[i][j]);
        }
        __syncthreads();
    }
#pragma unroll
    for (int i = 0; i < 4; i++) {
        int mi = m0 + ty * 4 + i;
        if (mi >= S_) continue;
#pragma unroll
        for (int j = 0; j < 4; j++) {
            int nj = n0 + tx * 4 + j;
            size_t off = (size_t)b * S_ * E_ + (size_t)mi * E_ + h * HD_ + nj;
            __nv_bfloat16 hi, lo;
            split1(acc[i][j], hi, lo);
            g_o_hi[off] = hi;
            g_o_lo[off] = lo;
        }
    }
}

// ============================================================================
// LayerNorm over [S,E] per batch
// ============================================================================
__global__ __launch_bounds__(256) void ln_partial(
    const float* __restrict__ A, const float* __restrict__ R)
{
    const int b = blockIdx.x, chunk = blockIdx.y;
    const size_t base = (size_t)b * LN_N + (size_t)chunk * LN_CH;
    float s = 0.f, sq = 0.f;
    for (int i = threadIdx.x; i < LN_CH; i += 256) {
        float v = A[base + i];
        if (R) v += R[base + i];
        s += v; sq += v * v;
    }
    __shared__ float ss[256], sb[256];
    ss[threadIdx.x] = s; sb[threadIdx.x] = sq;
    __syncthreads();
    for (int o = 128; o > 0; o >>= 1) {
        if (threadIdx.x < o) {
            ss[threadIdx.x] += ss[threadIdx.x + o];
            sb[threadIdx.x] += sb[threadIdx.x + o];
        }
        __syncthreads();
    }
    if (threadIdx.x == 0) {
        g_psum[b * LN_CHUNKS + chunk] = ss[0];
        g_psq [b * LN_CHUNKS + chunk] = sb[0];
    }
}

__global__ void ln_finalize()
{
    const int b = threadIdx.x;
    if (b >= B_) return;
    float s = 0.f, sq = 0.f;
#pragma unroll
    for (int i = 0; i < LN_CHUNKS; i++) {
        s  += g_psum[b * LN_CHUNKS + i];
        sq += g_psq [b * LN_CHUNKS + i];
    }
    const float inv_n = 1.0f / (float)LN_N;
    float mu = s * inv_n;
    float var = sq * inv_n - mu * mu;
    g_mu[b] = mu;
    g_rstd[b] = rsqrtf(var + 1e-5f);
}

// LN1 apply -> bf16 hi/lo
__global__ __launch_bounds__(256) void ln_apply_split(
    const float* __restrict__ A, const float* __restrict__ w,
    const float* __restrict__ bias)
{
    const int gid = blockIdx.x * 256 + threadIdx.x;
    if (gid >= NE_) return;
    const int b = gid / LN_N;
    const int r = gid - b * LN_N;
    float v = (A[gid] - g_mu[b]) * g_rstd[b] * w[r] + bias[r];
    __nv_bfloat16 hi, lo;
    split1(v, hi, lo);
    g_h_hi[gid] = hi;
    g_h_lo[gid] = lo;
}

// LN2 apply -> fp32 out
__global__ __launch_bounds__(256) void ln_apply(
    const float* __restrict__ A, const float* __restrict__ R,
    const float* __restrict__ w, const float* __restrict__ bias,
    float* __restrict__ out)
{
    const int gid = blockIdx.x * 256 + threadIdx.x;
    if (gid >= NE_) return;
    const int b = gid / LN_N;
    const int r = gid - b * LN_N;
    float v = A[gid] + R[gid];
    out[gid] = (v - g_mu[b]) * g_rstd[b] * w[r] + bias[r];
}

// ============================================================================
// Launch
// ============================================================================
extern "C" void kernel_launch(void* const* d_in, const int* in_sizes, int n_in,
                              void* d_out, int out_size)
{
    const float* x      = (const float*)d_in[0];
    const float* conv_w = (const float*)d_in[1];
    const float* conv_b = (const float*)d_in[2];
    const float* wq = (const float*)d_in[3];  const float* bq = (const float*)d_in[4];
    const float* wk = (const float*)d_in[5];  const float* bk = (const float*)d_in[6];
    const float* wv = (const float*)d_in[7];  const float* bv = (const float*)d_in[8];
    const float* wo = (const float*)d_in[9];  const float* bo = (const float*)d_in[10];
    const float* ln1w = (const float*)d_in[11]; const float* ln1b = (const float*)d_in[12];
    const float* ln2w = (const float*)d_in[13]; const float* ln2b = (const float*)d_in[14];
    float* out = (float*)d_out;

    float *emb, *q, *k, *v, *op;
    cudaGetSymbolAddress((void**)&emb, g_emb);
    cudaGetSymbolAddress((void**)&q,   g_q);
    cudaGetSymbolAddress((void**)&k,   g_k);
    cudaGetSymbolAddress((void**)&v,   g_v);
    cudaGetSymbolAddress((void**)&op,  g_op);
    __nv_bfloat16 *aph, *apl, *hh, *hl, *oh, *ol, *wh, *wl;
    cudaGetSymbolAddress((void**)&aph, g_ap_hi);
    cudaGetSymbolAddress((void**)&apl, g_ap_lo);
    cudaGetSymbolAddress((void**)&hh,  g_h_hi);
    cudaGetSymbolAddress((void**)&hl,  g_h_lo);
    cudaGetSymbolAddress((void**)&oh,  g_o_hi);
    cudaGetSymbolAddress((void**)&ol,  g_o_lo);
    cudaGetSymbolAddress((void**)&wh,  g_w_hi);
    cudaGetSymbolAddress((void**)&wl,  g_w_lo);

    const dim3 gemm_grid(6, 98);                       // 128x128 tiles
    const dim3 sc_grid(4, 4, B_ * H_);
    const dim3 av_grid(3, 4, B_ * H_);
    const dim3 lnp_grid(B_, LN_CHUNKS);
    const int  lna_blocks = NE_ / 256;
    const int  sm_blocks = (B_ * H_ * S_ * 32 + 255) / 256;
    const int  ws_blocks = (WN_ / 4 + 255) / 256;
    const int  ps_blocks = (NE_ / 4 + 255) / 256;

    // 0. weight + patch splits
    weight_split<<<ws_blocks, 256>>>(conv_w, wh + 0 * (size_t)WN_, wl + 0 * (size_t)WN_);
    weight_split<<<ws_blocks, 256>>>(wq,     wh + 1 * (size_t)WN_, wl + 1 * (size_t)WN_);
    weight_split<<<ws_blocks, 256>>>(wk,     wh + 2 * (size_t)WN_, wl + 2 * (size_t)WN_);
    weight_split<<<ws_blocks, 256>>>(wv,     wh + 3 * (size_t)WN_, wl + 3 * (size_t)WN_);
    weight_split<<<ws_blocks, 256>>>(wo,     wh + 4 * (size_t)WN_, wl + 4 * (size_t)WN_);
    patch_split<<<ps_blocks, 256>>>(x, aph, apl);
    // 1. patch embedding GEMM -> emb
    gemm_mma<<<gemm_grid, 256>>>(
        aph, apl, wh + 0 * (size_t)WN_, wl + 0 * (size_t)WN_, conv_b, emb);
    // 2. LN1 -> h (bf16 hi/lo)
    ln_partial<<<lnp_grid, 256>>>(emb, nullptr);
    ln_finalize<<<1, 64>>>();
    ln_apply_split<<<lna_blocks, 256>>>(emb, ln1w, ln1b);
    // 3. QKV
    gemm_mma<<<gemm_grid, 256>>>(
        hh, hl, wh + 1 * (size_t)WN_, wl + 1 * (size_t)WN_, bq, q);
    gemm_mma<<<gemm_grid, 256>>>(
        hh, hl, wh + 2 * (size_t)WN_, wl + 2 * (size_t)WN_, bk, k);
    gemm_mma<<<gemm_grid, 256>>>(
        hh, hl, wh + 3 * (size_t)WN_, wl + 3 * (size_t)WN_, bv, v);
    // 4. attention (fp32), AV writes bf16 hi/lo o
    attn_scores<<<sc_grid, 256>>>(q, k);
    softmax_rows<<<sm_blocks, 256>>>();
    attn_av<<<av_grid, 256>>>(v);
    // 5. output projection
    gemm_mma<<<gemm_grid, 256>>>(
        oh, ol, wh + 4 * (size_t)WN_, wl + 4 * (size_t)WN_, bo, op);
    // 6. residual + LN2 -> out
    ln_partial<<<lnp_grid, 256>>>(emb, op);
    ln_finalize<<<1, 64>>>();
    ln_apply<<<lna_blocks, 256>>>(emb, op, ln2w, ln2b, out);
}

// round 4
// speedup vs baseline: 1.8875x; 1.1786x over previous
#include <cuda_runtime.h>
#include <cuda_bf16.h>
#include <math.h>
#include <stdint.h>

// Problem constants
#define B_   64
#define S_   196
#define E_   768
#define H_   4
#define HD_  192
#define M_   (B_*S_)        // 12544
#define NE_  (B_*S_*E_)     // 9,633,792
#define LN_N (S_*E_)        // 150,528
#define LN_CHUNKS 8
#define LN_CH (LN_N/LN_CHUNKS)
#define WN_  (E_*E_)
#define SKP  224            // padded seq (K dim of AV, cols of attn rows)
#define NBH  (B_*H_)        // 256

// ---------------- scratch (device globals; no allocation allowed) ----------
__device__ __align__(256) float g_emb[NE_];
__device__ __align__(256) float g_op[NE_];
__device__ __align__(256) float g_scores[NBH*S_*SKP];       // fp32 logits
__device__ float g_psum[B_*LN_CHUNKS];
__device__ float g_psq[B_*LN_CHUNKS];
__device__ float g_mu[B_];
__device__ float g_rstd[B_];

__device__ __align__(256) __nv_bfloat16 g_ap_hi[NE_];
__device__ __align__(256) __nv_bfloat16 g_ap_lo[NE_];
__device__ __align__(256) __nv_bfloat16 g_h_hi[NE_];
__device__ __align__(256) __nv_bfloat16 g_h_lo[NE_];
__device__ __align__(256) __nv_bfloat16 g_q_hi[NE_];
__device__ __align__(256) __nv_bfloat16 g_q_lo[NE_];
__device__ __align__(256) __nv_bfloat16 g_k_hi[NE_];
__device__ __align__(256) __nv_bfloat16 g_k_lo[NE_];
__device__ __align__(256) __nv_bfloat16 g_vt_hi[NBH*HD_*SKP]; // V transposed per head
__device__ __align__(256) __nv_bfloat16 g_vt_lo[NBH*HD_*SKP];
__device__ __align__(256) __nv_bfloat16 g_at_hi[NBH*S_*SKP];  // attn probs
__device__ __align__(256) __nv_bfloat16 g_at_lo[NBH*S_*SKP];
__device__ __align__(256) __nv_bfloat16 g_o_hi[NE_];
__device__ __align__(256) __nv_bfloat16 g_o_lo[NE_];
__device__ __align__(256) __nv_bfloat16 g_w_hi[5][WN_];
__device__ __align__(256) __nv_bfloat16 g_w_lo[5][WN_];

// ============================================================================
// PTX helpers
// ============================================================================
__device__ __forceinline__ uint32_t smem_u32(const void* p) {
    uint32_t a;
    asm("{ .reg .u64 t; cvta.to.shared.u64 t, %1; cvt.u32.u64 %0, t; }"
        : "=r"(a) : "l"(p));
    return a;
}
__device__ __forceinline__ void ldsm_x4(uint32_t* r, uint32_t addr) {
    asm volatile("ldmatrix.sync.aligned.m8n8.x4.shared.b16 {%0,%1,%2,%3}, [%4];"
                 : "=r"(r[0]), "=r"(r[1]), "=r"(r[2]), "=r"(r[3]) : "r"(addr));
}
__device__ __forceinline__ void ldsm_x2(uint32_t* r, uint32_t addr) {
    asm volatile("ldmatrix.sync.aligned.m8n8.x2.shared.b16 {%0,%1}, [%2];"
                 : "=r"(r[0]), "=r"(r[1]) : "r"(addr));
}
__device__ __forceinline__ void mma16816(float* c, const uint32_t* a, const uint32_t* b) {
    asm volatile(
        "mma.sync.aligned.m16n8k16.row.col.f32.bf16.bf16.f32 "
        "{%0,%1,%2,%3}, {%4,%5,%6,%7}, {%8,%9}, {%0,%1,%2,%3};"
        : "+f"(c[0]), "+f"(c[1]), "+f"(c[2]), "+f"(c[3])
        : "r"(a[0]), "r"(a[1]), "r"(a[2]), "r"(a[3]), "r"(b[0]), "r"(b[1]));
}
__device__ __forceinline__ void cp16(uint32_t saddr, const void* gaddr) {
    asm volatile("cp.async.cg.shared.global [%0], [%1], 16;"
                 :: "r"(saddr), "l"(gaddr) : "memory");
}
#define CP_COMMIT() asm volatile("cp.async.commit_group;" ::: "memory")
#define CP_WAIT1()  asm volatile("cp.async.wait_group 1;" ::: "memory")

__device__ __forceinline__ void split1(float x, __nv_bfloat16& hi, __nv_bfloat16& lo) {
    hi = __float2bfloat16(x);
    lo = __float2bfloat16(x - __bfloat162float(hi));
}

// ============================================================================
// HMMA bf16-split GEMM, cp.async 3-stage pipeline.
//   C[m,n] = sum_k A[m,k]*B[n,k] + bias[n],  A*B ~= Ahi*Bhi + Alo*Bhi + Ahi*Blo
// M=12544, N=768, K=768. CTA 128x128, K-stage 32, 72 chunks. 8 warps, 64x32 wtile.
// mode 0: fp32 C.  mode 1: split hi/lo same layout.  mode 2: split + per-head transpose (V).
// ============================================================================
#define ASTR 40
#define STG_A 10240            // 128*40*2
#define STG_BYTES 20480
#define GEMM_SMEM (3 * STG_BYTES)

__global__ __launch_bounds__(256) void gemm_mma(
    const __nv_bfloat16* __restrict__ Ahi, const __nv_bfloat16* __restrict__ Alo,
    const __nv_bfloat16* __restrict__ Bhi, const __nv_bfloat16* __restrict__ Blo,
    const float* __restrict__ bias, float* __restrict__ C,
    __nv_bfloat16* __restrict__ Chi, __nv_bfloat16* __restrict__ Clo, int mode)
{
    extern __shared__ char smem[];
    const uint32_t sbase = smem_u32(smem);
    const int tid = threadIdx.x;
    const int wid = tid >> 5, lane = tid & 31;
    const int m0 = blockIdx.y * 128, n0 = blockIdx.x * 128;
    const int wm = (wid >> 2) * 64, wn = (wid & 3) * 32;
    const int lrow = tid >> 1, lcol = (tid & 1) * 16;

    float acc[4][4][4];
#pragma unroll
    for (int i = 0; i < 4; i++)
#pragma unroll
        for (int j = 0; j < 4; j++)
#pragma unroll
            for (int q = 0; q < 4; q++) acc[i][j][q] = 0.f;

    auto issue = [&](int c, int st) {
        const int seg = c / 24;
        const int k0 = (c - seg * 24) * 32 + lcol;
        const __nv_bfloat16* A = (seg == 1) ? Alo : Ahi;
        const __nv_bfloat16* B = (seg == 2) ? Blo : Bhi;
        const __nv_bfloat16* ap = A + (size_t)(m0 + lrow) * E_ + k0;
        const __nv_bfloat16* bp = B + (size_t)(n0 + lrow) * E_ + k0;
        const uint32_t da = sbase + st * STG_BYTES + lrow * 80 + lcol * 2;
        const uint32_t db = da + STG_A;
        cp16(da, ap); cp16(da + 16, ap + 8);
        cp16(db, bp); cp16(db + 16, bp + 8);
    };

    const int arow = wm + (lane & 15);
    const int akoff = (lane >> 4) * 8;
    const int brow = wn + (lane & 7);
    const int bkoff = ((lane >> 3) & 1) * 8;

    issue(0, 0); CP_COMMIT();
    issue(1, 1); CP_COMMIT();

    for (int c = 0; c < 72; c++) {
        const int st = c - (c / 3) * 3;         // c % 3
        CP_WAIT1();
        __syncthreads();
        if (c + 2 < 72) {
            int ns = c + 2; ns -= (ns / 3) * 3;
            issue(c + 2, ns);
        }
        CP_COMMIT();
        const uint32_t aStage = sbase + st * STG_BYTES;
        const uint32_t bStage = aStage + STG_A;
#pragma unroll
        for (int ks = 0; ks < 2; ks++) {
            const int k = ks * 16;
            uint32_t af[4][4], bf[4][2];
#pragma unroll
            for (int mt = 0; mt < 4; mt++)
                ldsm_x4(af[mt], aStage + ((arow + mt * 16) * ASTR + k + akoff) * 2);
#pragma unroll
            for (int nt = 0; nt < 4; nt++)
                ldsm_x2(bf[nt], bStage + ((brow + nt * 8) * ASTR + k + bkoff) * 2);
#pragma unroll
            for (int mt = 0; mt < 4; mt++)
#pragma unroll
                for (int nt = 0; nt < 4; nt++)
                    mma16816(acc[mt][nt], af[mt], bf[nt]);
        }
    }

    const int erow = lane >> 2;
    const int ecol = (lane & 3) * 2;
#pragma unroll
    for (int mt = 0; mt < 4; mt++) {
#pragma unroll
        for (int nt = 0; nt < 4; nt++) {
            const int col = n0 + wn + nt * 8 + ecol;
            const float b0 = bias[col], b1 = bias[col + 1];
            const int r0 = m0 + wm + mt * 16 + erow;
            float v00 = acc[mt][nt][0] + b0, v01 = acc[mt][nt][1] + b1;
            float v10 = acc[mt][nt][2] + b0, v11 = acc[mt][nt][3] + b1;
            if (mode == 0) {
                *(float2*)&C[(size_t)r0 * E_ + col] = make_float2(v00, v01);
                *(float2*)&C[(size_t)(r0 + 8) * E_ + col] = make_float2(v10, v11);
            } else if (mode == 1) {
                __nv_bfloat16 h0, l0, h1, l1;
                split1(v00, h0, l0); split1(v01, h1, l1);
                size_t off = (size_t)r0 * E_ + col;
                *(__nv_bfloat162*)&Chi[off] = __nv_bfloat162(h0, h1);
                *(__nv_bfloat162*)&Clo[off] = __nv_bfloat162(l0, l1);
                split1(v10, h0, l0); split1(v11, h1, l1);
                off = (size_t)(r0 + 8) * E_ + col;
                *(__nv_bfloat162*)&Chi[off] = __nv_bfloat162(h0, h1);
                *(__nv_bfloat162*)&Clo[off] = __nv_bfloat162(l0, l1);
            } else {
                // V transpose: vT[(b*H + h)*HD + d][s], row stride SKP
                const int hh = col / HD_, d = col - hh * HD_;
#pragma unroll
                for (int rr = 0; rr < 2; rr++) {
                    const int r = r0 + rr * 8;
                    const int bb = r / S_, s = r - bb * S_;
                    const float va = rr ? v10 : v00;
                    const float vb = rr ? v11 : v01;
                    __nv_bfloat16 h0, l0;
                    size_t o0 = ((size_t)(bb * H_ + hh) * HD_ + d) * SKP + s;
                    split1(va, h0, l0); Chi[o0] = h0; Clo[o0] = l0;
                    split1(vb, h0, l0); Chi[o0 + SKP] = h0; Clo[o0 + SKP] = l0;
                }
            }
        }
    }
}

// ============================================================================
// Attention scores via HMMA: S[bh,m,n] = scale * q[m,:] . k[n,:]  (3-term split)
// per bh: M=N=196 (tiles 64), K=192*3 terms -> 18 chunks of 32.
// ============================================================================
#define SC_STG (64 * ASTR)    // bf16 elems per stage matrix

__global__ __launch_bounds__(128) void scores_mma()
{
    __shared__ __nv_bfloat16 As[2][64][ASTR];
    __shared__ __nv_bfloat16 Bs[2][64][ASTR];
    const int bh = blockIdx.z;
    const int b = bh >> 2, h = bh & 3;
    const int tid = threadIdx.x;
    const int wid = tid >> 5, lane = tid & 31;
    const int m0 = blockIdx.y * 64, n0 = blockIdx.x * 64;
    const int wm = (wid >> 1) * 32, wn = (wid & 1) * 32;
    const int lrow = tid >> 1, lcol = (tid & 1) * 16;

    float acc[2][4][4];
#pragma unroll
    for (int i = 0; i < 2; i++)
#pragma unroll
        for (int j = 0; j < 4; j++)
#pragma unroll
            for (int q = 0; q < 4; q++) acc[i][j][q] = 0.f;

    const int marow = m0 + lrow, mclamp = marow < S_ ? marow : S_ - 1;
    const int narow = n0 + lrow, nclamp = narow < S_ ? narow : S_ - 1;
    uint4 ra0, ra1, rb0, rb1;
    auto gload = [&](int c) {
        const int seg = c / 6;
        const int k0 = (c - seg * 6) * 32 + lcol;
        const __nv_bfloat16* A = (seg == 1) ? g_q_lo : g_q_hi;
        const __nv_bfloat16* B = (seg == 2) ? g_k_lo : g_k_hi;
        const __nv_bfloat16* ap = A + (size_t)(b * S_ + mclamp) * E_ + h * HD_ + k0;
        const __nv_bfloat16* bp = B + (size_t)(b * S_ + nclamp) * E_ + h * HD_ + k0;
        ra0 = *(const uint4*)ap; ra1 = *(const uint4*)(ap + 8);
        rb0 = *(const uint4*)bp; rb1 = *(const uint4*)(bp + 8);
    };
    auto sstore = [&](int st) {
        *(uint4*)&As[st][lrow][lcol] = ra0; *(uint4*)&As[st][lrow][lcol + 8] = ra1;
        *(uint4*)&Bs[st][lrow][lcol] = rb0; *(uint4*)&Bs[st][lrow][lcol + 8] = rb1;
    };

    const uint32_t aBase = smem_u32(&As[0][0][0]);
    const uint32_t bBase = smem_u32(&Bs[0][0][0]);
    const int arow = wm + (lane & 15);
    const int akoff = (lane >> 4) * 8;
    const int brow = wn + (lane & 7);
    const int bkoff = ((lane >> 3) & 1) * 8;

    gload(0); sstore(0);
    __syncthreads();
    for (int c = 0; c < 18; c++) {
        const int st = c & 1;
        if (c + 1 < 18) gload(c + 1);
        const uint32_t aS = aBase + st * SC_STG * 2;
        const uint32_t bS = bBase + st * SC_STG * 2;
#pragma unroll
        for (int ks = 0; ks < 2; ks++) {
            const int k = ks * 16;
            uint32_t af[2][4], bf[4][2];
#pragma unroll
            for (int mt = 0; mt < 2; mt++)
                ldsm_x4(af[mt], aS + ((arow + mt * 16) * ASTR + k + akoff) * 2);
#pragma unroll
            for (int nt = 0; nt < 4; nt++)
                ldsm_x2(bf[nt], bS + ((brow + nt * 8) * ASTR + k + bkoff) * 2);
#pragma unroll
            for (int mt = 0; mt < 2; mt++)
#pragma unroll
                for (int nt = 0; nt < 4; nt++)
                    mma16816(acc[mt][nt], af[mt], bf[nt]);
        }
        if (c + 1 < 18) sstore(st ^ 1);
        __syncthreads();
    }

    const float scale = rsqrtf((float)HD_);
    const int erow = lane >> 2, ecol = (lane & 3) * 2;
    float* Sp = g_scores + (size_t)bh * S_ * SKP;
#pragma unroll
    for (int mt = 0; mt < 2; mt++) {
#pragma unroll
        for (int nt = 0; nt < 4; nt++) {
            const int col = n0 + wn + nt * 8 + ecol;
            if (col >= S_) continue;
            const int r0 = m0 + wm + mt * 16 + erow;
            if (r0 < S_)
                *(float2*)&Sp[(size_t)r0 * SKP + col] =
                    make_float2(acc[mt][nt][0] * scale, acc[mt][nt][1] * scale);
            if (r0 + 8 < S_)
                *(float2*)&Sp[(size_t)(r0 + 8) * SKP + col] =
                    make_float2(acc[mt][nt][2] * scale, acc[mt][nt][3] * scale);
        }
    }
}

// ============================================================================
// Softmax rows: read fp32 logits, write bf16 hi/lo probs (224 cols, zero pad)
// ============================================================================
__global__ __launch_bounds__(256) void softmax_rows()
{
    const int row = (blockIdx.x * blockDim.x + threadIdx.x) >> 5;
    const int lane = threadIdx.x & 31;
    if (row >= NBH * S_) return;
    const float* p = g_scores + (size_t)row * SKP;
    float v[7];
    float mx = -1e30f;
#pragma unroll
    for (int i = 0; i < 7; i++) {
        int j = lane + i * 32;
        v[i] = (j < S_) ? p[j] : -1e30f;
        mx = fmaxf(mx, v[i]);
    }
#pragma unroll
    for (int o = 16; o > 0; o >>= 1) mx = fmaxf(mx, __shfl_xor_sync(0xFFFFFFFFu, mx, o));
    float sum = 0.f;
#pragma unroll
    for (int i = 0; i < 7; i++) {
        int j = lane + i * 32;
        v[i] = (j < S_) ? __expf(v[i] - mx) : 0.f;
        sum += v[i];
    }
#pragma unroll
    for (int o = 16; o > 0; o >>= 1) sum += __shfl_xor_sync(0xFFFFFFFFu, sum, o);
    const float inv = 1.0f / sum;
    __nv_bfloat16* ah = g_at_hi + (size_t)row * SKP;
    __nv_bfloat16* al = g_at_lo + (size_t)row * SKP;
#pragma unroll
    for (int i = 0; i < 7; i++) {
        int j = lane + i * 32;
        float val = (j < S_) ? v[i] * inv : 0.f;
        __nv_bfloat16 hi, lo;
        split1(val, hi, lo);
        ah[j] = hi; al[j] = lo;
    }
}

// zero the vT pad columns s in [196,224)
__global__ __launch_bounds__(256) void vt_zero()
{
    const int gid = blockIdx.x * 256 + threadIdx.x;
    const int total = NBH * HD_ * (SKP - S_);
    if (gid >= total) return;
    const int row = gid / (SKP - S_);
    const int s = S_ + gid - row * (SKP - S_);
    g_vt_hi[(size_t)row * SKP + s] = __float2bfloat16(0.f);
    g_vt_lo[(size_t)row * SKP + s] = __float2bfloat16(0.f);
}

// ============================================================================
// AV via HMMA: o[bh,m,d] = sum_j attn[m,j] * vT[d,j]   (3-term split)
// per bh: M=196 (4 tiles), N=192 (3 tiles), K=224*3 -> 21 chunks of 32.
// ============================================================================
__global__ __launch_bounds__(128) void av_mma()
{
    __shared__ __nv_bfloat16 As[2][64][ASTR];
    __shared__ __nv_bfloat16 Bs[2][64][ASTR];
    const int bh = blockIdx.z;
    const int b = bh >> 2, h = bh & 3;
    const int tid = threadIdx.x;
    const int wid = tid >> 5, lane = tid & 31;
    const int m0 = blockIdx.y * 64, n0 = blockIdx.x * 64;
    const int wm = (wid >> 1) * 32, wn = (wid & 1) * 32;
    const int lrow = tid >> 1, lcol = (tid & 1) * 16;

    float acc[2][4][4];
#pragma unroll
    for (int i = 0; i < 2; i++)
#pragma unroll
        for (int j = 0; j < 4; j++)
#pragma unroll
            for (int q = 0; q < 4; q++) acc[i][j][q] = 0.f;

    const int marow = m0 + lrow, mclamp = marow < S_ ? marow : S_ - 1;
    uint4 ra0, ra1, rb0, rb1;
    auto gload = [&](int c) {
        const int seg = c / 7;
        const int k0 = (c - seg * 7) * 32 + lcol;
        const __nv_bfloat16* A = (seg == 1) ? g_at_lo : g_at_hi;
        const __nv_bfloat16* B = (seg == 2) ? g_vt_lo : g_vt_hi;
        const __nv_bfloat16* ap = A + ((size_t)bh * S_ + mclamp) * SKP + k0;
        const __nv_bfloat16* bp = B + ((size_t)bh * HD_ + n0 + lrow) * SKP + k0;
        ra0 = *(const uint4*)ap; ra1 = *(const uint4*)(ap + 8);
        rb0 = *(const uint4*)bp; rb1 = *(const uint4*)(bp + 8);
    };
    auto sstore = [&](int st) {
        *(uint4*)&As[st][lrow][lcol] = ra0; *(uint4*)&As[st][lrow][lcol + 8] = ra1;
        *(uint4*)&Bs[st][lrow][lcol] = rb0; *(uint4*)&Bs[st][lrow][lcol + 8] = rb1;
    };

    const uint32_t aBase = smem_u32(&As[0][0][0]);
    const uint32_t bBase = smem_u32(&Bs[0][0][0]);
    const int arow = wm + (lane & 15);
    const int akoff = (lane >> 4) * 8;
    const int brow = wn + (lane & 7);
    const int bkoff = ((lane >> 3) & 1) * 8;

    gload(0); sstore(0);
    __syncthreads();
    for (int c = 0; c < 21; c++) {
        const int st = c & 1;
        if (c + 1 < 21) gload(c + 1);
        const uint32_t aS = aBase + st * SC_STG * 2;
        const uint32_t bS = bBase + st * SC_STG * 2;
#pragma unroll
        for (int ks = 0; ks < 2; ks++) {
            const int k = ks * 16;
            uint32_t af[2][4], bf[4][2];
#pragma unroll
            for (int mt = 0; mt < 2; mt++)
                ldsm_x4(af[mt], aS + ((arow + mt * 16) * ASTR + k + akoff) * 2);
#pragma unroll
            for (int nt = 0; nt < 4; nt++)
                ldsm_x2(bf[nt], bS + ((brow + nt * 8) * ASTR + k + bkoff) * 2);
#pragma unroll
            for (int mt = 0; mt < 2; mt++)
#pragma unroll
                for (int nt = 0; nt < 4; nt++)
                    mma16816(acc[mt][nt], af[mt], bf[nt]);
        }
        if (c + 1 < 21) sstore(st ^ 1);
        __syncthreads();
    }

    const int erow = lane >> 2, ecol = (lane & 3) * 2;
#pragma unroll
    for (int mt = 0; mt < 2; mt++) {
#pragma unroll
        for (int nt = 0; nt < 4; nt++) {
            const int col = n0 + wn + nt * 8 + ecol;   // < 192 always
            const int r0 = m0 + wm + mt * 16 + erow;
#pragma unroll
            for (int rr = 0; rr < 2; rr++) {
                const int r = r0 + rr * 8;
                if (r >= S_) continue;
                const float va = acc[mt][nt][rr * 2 + 0];
                const float vb = acc[mt][nt][rr * 2 + 1];
                __nv_bfloat16 h0, l0, h1, l1;
                split1(va, h0, l0); split1(vb, h1, l1);
                const size_t off = ((size_t)(b * S_ + r)) * E_ + h * HD_ + col;
                *(__nv_bfloat162*)&g_o_hi[off] = __nv_bfloat162(h0, h1);
                *(__nv_bfloat162*)&g_o_lo[off] = __nv_bfloat162(l0, l1);
            }
        }
    }
}

// ============================================================================
// Splits
// ============================================================================
__global__ __launch_bounds__(256) void weight_split(
    const float* __restrict__ w, __nv_bfloat16* __restrict__ hi,
    __nv_bfloat16* __restrict__ lo)
{
    const int gid = blockIdx.x * 256 + threadIdx.x;
    if (gid >= WN_ / 4) return;
    float4 v = *(const float4*)(w + gid * 4);
    __nv_bfloat16 h0, l0;
#pragma unroll
    for (int i = 0; i < 4; i++) {
        split1((&v.x)[i], h0, l0);
        hi[gid * 4 + i] = h0;
        lo[gid * 4 + i] = l0;
    }
}

__global__ __launch_bounds__(256) void patch_split(
    const float* __restrict__ x, __nv_bfloat16* __restrict__ hi,
    __nv_bfloat16* __restrict__ lo)
{
    const int gid = blockIdx.x * 256 + threadIdx.x;
    if (gid >= NE_ / 4) return;
    const int m = gid / 192;
    const int k = (gid - m * 192) * 4;
    const int b = m / S_;
    const int s = m - b * S_;
    const int gy = s / 14, gx = s - gy * 14;
    const int c = k >> 8;
    const int py = (k >> 4) & 15;
    const int px = k & 15;
    const float* src = x + ((((size_t)b * 3 + c) * 224 + gy * 16 + py) * 224 + gx * 16 + px);
    float4 v = *(const float4*)src;
    const size_t o = (size_t)m * E_ + k;
    __nv_bfloat16 h0, l0;
#pragma unroll
    for (int i = 0; i < 4; i++) {
        split1((&v.x)[i], h0, l0);
        hi[o + i] = h0;
        lo[o + i] = l0;
    }
}

// ============================================================================
// LayerNorm over [S,E] per batch
// ============================================================================
__global__ __launch_bounds__(256) void ln_partial(
    const float* __restrict__ A, const float* __restrict__ R)
{
    const int b = blockIdx.x, chunk = blockIdx.y;
    const size_t base = (size_t)b * LN_N + (size_t)chunk * LN_CH;
    float s = 0.f, sq = 0.f;
    for (int i = threadIdx.x; i < LN_CH; i += 256) {
        float v = A[base + i];
        if (R) v += R[base + i];
        s += v; sq += v * v;
    }
    __shared__ float ss[256], sb[256];
    ss[threadIdx.x] = s; sb[threadIdx.x] = sq;
    __syncthreads();
    for (int o = 128; o > 0; o >>= 1) {
        if (threadIdx.x < o) {
            ss[threadIdx.x] += ss[threadIdx.x + o];
            sb[threadIdx.x] += sb[threadIdx.x + o];
        }
        __syncthreads();
    }
    if (threadIdx.x == 0) {
        g_psum[b * LN_CHUNKS + chunk] = ss[0];
        g_psq [b * LN_CHUNKS + chunk] = sb[0];
    }
}

__global__ void ln_finalize()
{
    const int b = threadIdx.x;
    if (b >= B_) return;
    float s = 0.f, sq = 0.f;
#pragma unroll
    for (int i = 0; i < LN_CHUNKS; i++) {
        s  += g_psum[b * LN_CHUNKS + i];
        sq += g_psq [b * LN_CHUNKS + i];
    }
    const float inv_n = 1.0f / (float)LN_N;
    float mu = s * inv_n;
    float var = sq * inv_n - mu * mu;
    g_mu[b] = mu;
    g_rstd[b] = rsqrtf(var + 1e-5f);
}

__global__ __launch_bounds__(256) void ln_apply_split(
    const float* __restrict__ A, const float* __restrict__ w,
    const float* __restrict__ bias)
{
    const int gid = blockIdx.x * 256 + threadIdx.x;
    if (gid >= NE_) return;
    const int b = gid / LN_N;
    const int r = gid - b * LN_N;
    float v = (A[gid] - g_mu[b]) * g_rstd[b] * w[r] + bias[r];
    __nv_bfloat16 hi, lo;
    split1(v, hi, lo);
    g_h_hi[gid] = hi;
    g_h_lo[gid] = lo;
}

__global__ __launch_bounds__(256) void ln_apply(
    const float* __restrict__ A, const float* __restrict__ R,
    const float* __restrict__ w, const float* __restrict__ bias,
    float* __restrict__ out)
{
    const int gid = blockIdx.x * 256 + threadIdx.x;
    if (gid >= NE_) return;
    const int b = gid / LN_N;
    const int r = gid - b * LN_N;
    float v = A[gid] + R[gid];
    out[gid] = (v - g_mu[b]) * g_rstd[b] * w[r] + bias[r];
}

// ============================================================================
// Launch
// ============================================================================
extern "C" void kernel_launch(void* const* d_in, const int* in_sizes, int n_in,
                              void* d_out, int out_size)
{
    const float* x      = (const float*)d_in[0];
    const float* conv_w = (const float*)d_in[1];
    const float* conv_b = (const float*)d_in[2];
    const float* wq = (const float*)d_in[3];  const float* bq = (const float*)d_in[4];
    const float* wk = (const float*)d_in[5];  const float* bk = (const float*)d_in[6];
    const float* wv = (const float*)d_in[7];  const float* bv = (const float*)d_in[8];
    const float* wo = (const float*)d_in[9];  const float* bo = (const float*)d_in[10];
    const float* ln1w = (const float*)d_in[11]; const float* ln1b = (const float*)d_in[12];
    const float* ln2w = (const float*)d_in[13]; const float* ln2b = (const float*)d_in[14];
    float* out = (float*)d_out;

    float *emb, *op;
    cudaGetSymbolAddress((void**)&emb, g_emb);
    cudaGetSymbolAddress((void**)&op,  g_op);
    __nv_bfloat16 *aph, *apl, *hh, *hl, *qh, *ql, *kh, *kl, *vth, *vtl, *oh, *ol, *wh, *wl;
    cudaGetSymbolAddress((void**)&aph, g_ap_hi);
    cudaGetSymbolAddress((void**)&apl, g_ap_lo);
    cudaGetSymbolAddress((void**)&hh,  g_h_hi);
    cudaGetSymbolAddress((void**)&hl,  g_h_lo);
    cudaGetSymbolAddress((void**)&qh,  g_q_hi);
    cudaGetSymbolAddress((void**)&ql,  g_q_lo);
    cudaGetSymbolAddress((void**)&kh,  g_k_hi);
    cudaGetSymbolAddress((void**)&kl,  g_k_lo);
    cudaGetSymbolAddress((void**)&vth, g_vt_hi);
    cudaGetSymbolAddress((void**)&vtl, g_vt_lo);
    cudaGetSymbolAddress((void**)&oh,  g_o_hi);
    cudaGetSymbolAddress((void**)&ol,  g_o_lo);
    cudaGetSymbolAddress((void**)&wh,  g_w_hi);
    cudaGetSymbolAddress((void**)&wl,  g_w_lo);

    cudaFuncSetAttribute(gemm_mma, cudaFuncAttributeMaxDynamicSharedMemorySize, GEMM_SMEM);

    const dim3 gemm_grid(6, 98);
    const dim3 sc_grid(4, 4, NBH);
    const dim3 av_grid(3, 4, NBH);
    const dim3 lnp_grid(B_, LN_CHUNKS);
    const int  lna_blocks = NE_ / 256;
    const int  sm_blocks = (NBH * S_ * 32 + 255) / 256;
    const int  ws_blocks = (WN_ / 4 + 255) / 256;
    const int  ps_blocks = (NE_ / 4 + 255) / 256;
    const int  vz_blocks = (NBH * HD_ * (SKP - S_) + 255) / 256;

    // 0. splits
    weight_split<<<ws_blocks, 256>>>(conv_w, wh + 0 * (size_t)WN_, wl + 0 * (size_t)WN_);
    weight_split<<<ws_blocks, 256>>>(wq,     wh + 1 * (size_t)WN_, wl + 1 * (size_t)WN_);
    weight_split<<<ws_blocks, 256>>>(wk,     wh + 2 * (size_t)WN_, wl + 2 * (size_t)WN_);
    weight_split<<<ws_blocks, 256>>>(wv,     wh + 3 * (size_t)WN_, wl + 3 * (size_t)WN_);
    weight_split<<<ws_blocks, 256>>>(wo,     wh + 4 * (size_t)WN_, wl + 4 * (size_t)WN_);
    patch_split<<<ps_blocks, 256>>>(x, aph, apl);
    vt_zero<<<vz_blocks, 256>>>();
    // 1. patch embedding -> emb (fp32)
    gemm_mma<<<gemm_grid, 256, GEMM_SMEM>>>(
        aph, apl, wh + 0 * (size_t)WN_, wl + 0 * (size_t)WN_, conv_b, emb, nullptr, nullptr, 0);
    // 2. LN1 -> h hi/lo
    ln_partial<<<lnp_grid, 256>>>(emb, nullptr);
    ln_finalize<<<1, 64>>>();
    ln_apply_split<<<lna_blocks, 256>>>(emb, ln1w, ln1b);
    // 3. QKV (bf16 hi/lo epilogues; V transposed per head)
    gemm_mma<<<gemm_grid, 256, GEMM_SMEM>>>(
        hh, hl, wh + 1 * (size_t)WN_, wl + 1 * (size_t)WN_, bq, nullptr, qh, ql, 1);
    gemm_mma<<<gemm_grid, 256, GEMM_SMEM>>>(
        hh, hl, wh + 2 * (size_t)WN_, wl + 2 * (size_t)WN_, bk, nullptr, kh, kl, 1);
    gemm_mma<<<gemm_grid, 256, GEMM_SMEM>>>(
        hh, hl, wh + 3 * (size_t)WN_, wl + 3 * (size_t)WN_, bv, nullptr, vth, vtl, 2);
    // 4. attention (all HMMA)
    scores_mma<<<sc_grid, 128>>>();
    softmax_rows<<<sm_blocks, 256>>>();
    av_mma<<<av_grid, 128>>>();
    // 5. output projection -> op (fp32)
    gemm_mma<<<gemm_grid, 256, GEMM_SMEM>>>(
        oh, ol, wh + 4 * (size_t)WN_, wl + 4 * (size_t)WN_, bo, op, nullptr, nullptr, 0);
    // 6. residual + LN2 -> out
    ln_partial<<<lnp_grid, 256>>>(emb, op);
    ln_finalize<<<1, 64>>>();
    ln_apply<<<lna_blocks, 256>>>(emb, op, ln2w, ln2b, out);
}

// round 5
// speedup vs baseline: 2.2522x; 1.1932x over previous
#include <cuda_runtime.h>
#include <cuda_bf16.h>
#include <math.h>
#include <stdint.h>

// Problem constants
#define B_   64
#define S_   196
#define E_   768
#define H_   4
#define HD_  192
#define M_   (B_*S_)        // 12544
#define NE_  (B_*S_*E_)     // 9,633,792
#define LN_N (S_*E_)        // 150,528
#define LN_CHUNKS 8
#define LN_CH (LN_N/LN_CHUNKS)
#define WN_  (E_*E_)
#define SKP  224            // padded seq
#define NBH  (B_*H_)        // 256

// ---------------- scratch (device globals) ----------------
__device__ __align__(256) float g_emb[NE_];
__device__ __align__(256) float g_op[NE_];
__device__ __align__(256) float g_scores[NBH*S_*SKP];
__device__ float g_psum[B_*LN_CHUNKS];
__device__ float g_psq[B_*LN_CHUNKS];
__device__ float g_mu[B_];
__device__ float g_rstd[B_];

__device__ __align__(256) __nv_bfloat16 g_ap_hi[NE_];
__device__ __align__(256) __nv_bfloat16 g_ap_lo[NE_];
__device__ __align__(256) __nv_bfloat16 g_h_hi[NE_];
__device__ __align__(256) __nv_bfloat16 g_h_lo[NE_];
__device__ __align__(256) __nv_bfloat16 g_q_hi[NE_];
__device__ __align__(256) __nv_bfloat16 g_q_lo[NE_];
__device__ __align__(256) __nv_bfloat16 g_k_hi[NE_];
__device__ __align__(256) __nv_bfloat16 g_k_lo[NE_];
__device__ __align__(256) __nv_bfloat16 g_vt_hi[NBH*HD_*SKP];
__device__ __align__(256) __nv_bfloat16 g_vt_lo[NBH*HD_*SKP];
__device__ __align__(256) __nv_bfloat16 g_at_hi[NBH*S_*SKP];
__device__ __align__(256) __nv_bfloat16 g_at_lo[NBH*S_*SKP];
__device__ __align__(256) __nv_bfloat16 g_o_hi[NE_];
__device__ __align__(256) __nv_bfloat16 g_o_lo[NE_];
__device__ __align__(256) __nv_bfloat16 g_w_hi[5][WN_];
__device__ __align__(256) __nv_bfloat16 g_w_lo[5][WN_];

// ============================================================================
// PTX helpers
// ============================================================================
__device__ __forceinline__ uint32_t smem_u32(const void* p) {
    uint32_t a;
    asm("{ .reg .u64 t; cvta.to.shared.u64 t, %1; cvt.u32.u64 %0, t; }"
        : "=r"(a) : "l"(p));
    return a;
}
__device__ __forceinline__ void ldsm_x4(uint32_t* r, uint32_t addr) {
    asm volatile("ldmatrix.sync.aligned.m8n8.x4.shared.b16 {%0,%1,%2,%3}, [%4];"
                 : "=r"(r[0]), "=r"(r[1]), "=r"(r[2]), "=r"(r[3]) : "r"(addr));
}
__device__ __forceinline__ void ldsm_x2(uint32_t* r, uint32_t addr) {
    asm volatile("ldmatrix.sync.aligned.m8n8.x2.shared.b16 {%0,%1}, [%2];"
                 : "=r"(r[0]), "=r"(r[1]) : "r"(addr));
}
__device__ __forceinline__ void mma16816(float* c, const uint32_t* a, const uint32_t* b) {
    asm volatile(
        "mma.sync.aligned.m16n8k16.row.col.f32.bf16.bf16.f32 "
        "{%0,%1,%2,%3}, {%4,%5,%6,%7}, {%8,%9}, {%0,%1,%2,%3};"
        : "+f"(c[0]), "+f"(c[1]), "+f"(c[2]), "+f"(c[3])
        : "r"(a[0]), "r"(a[1]), "r"(a[2]), "r"(a[3]), "r"(b[0]), "r"(b[1]));
}
__device__ __forceinline__ void cp16(uint32_t saddr, const void* gaddr) {
    asm volatile("cp.async.cg.shared.global [%0], [%1], 16;"
                 :: "r"(saddr), "l"(gaddr) : "memory");
}
#define CP_COMMIT() asm volatile("cp.async.commit_group;" ::: "memory")
#define CP_WAIT1()  asm volatile("cp.async.wait_group 1;" ::: "memory")

__device__ __forceinline__ void split1(float x, __nv_bfloat16& hi, __nv_bfloat16& lo) {
    hi = __float2bfloat16(x);
    lo = __float2bfloat16(x - __bfloat162float(hi));
}

// ============================================================================
// HMMA bf16-split GEMM, cp.async 3-stage pipeline.
// CTA 256x128, K-stage 64, 36 chunks (3 terms x 12). 8 warps, warp tile 64x64.
// mode 0: fp32 C.  mode 1: split hi/lo.  mode 2: split + per-head transpose (V).
// ============================================================================
#define ASTR 72
#define ROWB 144                 // 72 bf16 per smem row
#define A_STG (256 * ROWB)       // 36864
#define B_STG (128 * ROWB)       // 18432
#define STG_BYTES (A_STG + B_STG) // 55296
#define GEMM_SMEM (3 * STG_BYTES) // 165888

__global__ __launch_bounds__(256, 1) void gemm_mma(
    const __nv_bfloat16* __restrict__ Ahi, const __nv_bfloat16* __restrict__ Alo,
    const __nv_bfloat16* __restrict__ Bhi, const __nv_bfloat16* __restrict__ Blo,
    const float* __restrict__ bias, float* __restrict__ C,
    __nv_bfloat16* __restrict__ Chi, __nv_bfloat16* __restrict__ Clo, int mode)
{
    extern __shared__ char smem[];
    const uint32_t sbase = smem_u32(smem);
    const int tid = threadIdx.x;
    const int wid = tid >> 5, lane = tid & 31;
    const int m0 = blockIdx.y * 256, n0 = blockIdx.x * 128;
    const int wm = (wid >> 1) * 64, wn = (wid & 1) * 64;
    const int lr = tid >> 3, lseg = tid & 7;   // loader: 32 rows x 8 segs

    float acc[4][8][4];
#pragma unroll
    for (int i = 0; i < 4; i++)
#pragma unroll
        for (int j = 0; j < 8; j++)
#pragma unroll
            for (int q = 0; q < 4; q++) acc[i][j][q] = 0.f;

    auto issue = [&](int c, int st) {
        const int term = c / 12;
        const int k0 = (c - term * 12) * 64 + lseg * 8;
        const __nv_bfloat16* A = (term == 1) ? Alo : Ahi;
        const __nv_bfloat16* B = (term == 2) ? Blo : Bhi;
        const uint32_t base = sbase + st * STG_BYTES;
#pragma unroll
        for (int i = 0; i < 8; i++) {
            const int row = i * 32 + lr;
            cp16(base + row * ROWB + lseg * 16,
                 A + (size_t)(m0 + row) * E_ + k0);
        }
#pragma unroll
        for (int i = 0; i < 4; i++) {
            const int row = i * 32 + lr;
            cp16(base + A_STG + row * ROWB + lseg * 16,
                 B + (size_t)(n0 + row) * E_ + k0);
        }
    };

    // ldsm lane addressing
    const int arow = wm + (lane & 15);          // + mt*16
    const int akoff = (lane >> 4) * 8;
    const int brow = wn + (lane & 7) + ((lane >> 4) << 3);  // + nt2*16
    const int bkoff = ((lane >> 3) & 1) * 8;

    issue(0, 0); CP_COMMIT();
    issue(1, 1); CP_COMMIT();

    for (int c = 0; c < 36; c++) {
        const int st = c - (c / 3) * 3;
        CP_WAIT1();
        __syncthreads();
        if (c + 2 < 36) {
            int ns = c + 2; ns -= (ns / 3) * 3;
            issue(c + 2, ns);
        }
        CP_COMMIT();
        const uint32_t aStage = sbase + st * STG_BYTES;
        const uint32_t bStage = aStage + A_STG;
#pragma unroll
        for (int ks = 0; ks < 4; ks++) {
            const int k = ks * 16;
            uint32_t af[4][4], bf[4][4];
#pragma unroll
            for (int mt = 0; mt < 4; mt++)
                ldsm_x4(af[mt], aStage + ((arow + mt * 16) * ASTR + k + akoff) * 2);
#pragma unroll
            for (int nt2 = 0; nt2 < 4; nt2++)
                ldsm_x4(bf[nt2], bStage + ((brow + nt2 * 16) * ASTR + k + bkoff) * 2);
#pragma unroll
            for (int mt = 0; mt < 4; mt++)
#pragma unroll
                for (int nt = 0; nt < 8; nt++)
                    mma16816(acc[mt][nt], af[mt], &bf[nt >> 1][(nt & 1) * 2]);
        }
    }

    const int erow = lane >> 2;
    const int ecol = (lane & 3) * 2;
#pragma unroll
    for (int mt = 0; mt < 4; mt++) {
#pragma unroll
        for (int nt = 0; nt < 8; nt++) {
            const int col = n0 + wn + nt * 8 + ecol;
            const float b0 = bias[col], b1 = bias[col + 1];
            const int r0 = m0 + wm + mt * 16 + erow;
            float v00 = acc[mt][nt][0] + b0, v01 = acc[mt][nt][1] + b1;
            float v10 = acc[mt][nt][2] + b0, v11 = acc[mt][nt][3] + b1;
            if (mode == 0) {
                *(float2*)&C[(size_t)r0 * E_ + col] = make_float2(v00, v01);
                *(float2*)&C[(size_t)(r0 + 8) * E_ + col] = make_float2(v10, v11);
            } else if (mode == 1) {
                __nv_bfloat16 h0, l0, h1, l1;
                split1(v00, h0, l0); split1(v01, h1, l1);
                size_t off = (size_t)r0 * E_ + col;
                *(__nv_bfloat162*)&Chi[off] = __nv_bfloat162(h0, h1);
                *(__nv_bfloat162*)&Clo[off] = __nv_bfloat162(l0, l1);
                split1(v10, h0, l0); split1(v11, h1, l1);
                off = (size_t)(r0 + 8) * E_ + col;
                *(__nv_bfloat162*)&Chi[off] = __nv_bfloat162(h0, h1);
                *(__nv_bfloat162*)&Clo[off] = __nv_bfloat162(l0, l1);
            } else {
                const int hh = col / HD_, d = col - hh * HD_;
#pragma unroll
                for (int rr = 0; rr < 2; rr++) {
                    const int r = r0 + rr * 8;
                    const int bb = r / S_, s = r - bb * S_;
                    const float va = rr ? v10 : v00;
                    const float vb = rr ? v11 : v01;
                    __nv_bfloat16 h0, l0;
                    size_t o0 = ((size_t)(bb * H_ + hh) * HD_ + d) * SKP + s;
                    split1(va, h0, l0); Chi[o0] = h0; Clo[o0] = l0;
                    split1(vb, h0, l0); Chi[o0 + SKP] = h0; Clo[o0 + SKP] = l0;
                }
            }
        }
    }
}

// ============================================================================
// Attention scores via HMMA (64x64 tiles, 4 warps of 32x32)
// ============================================================================
#define SSTR 40
#define SC_STG (64 * SSTR)

__global__ __launch_bounds__(128) void scores_mma()
{
    __shared__ __nv_bfloat16 As[2][64][SSTR];
    __shared__ __nv_bfloat16 Bs[2][64][SSTR];
    const int bh = blockIdx.z;
    const int b = bh >> 2, h = bh & 3;
    const int tid = threadIdx.x;
    const int wid = tid >> 5, lane = tid & 31;
    const int m0 = blockIdx.y * 64, n0 = blockIdx.x * 64;
    const int wm = (wid >> 1) * 32, wn = (wid & 1) * 32;
    const int lrow = tid >> 1, lcol = (tid & 1) * 16;

    float acc[2][4][4];
#pragma unroll
    for (int i = 0; i < 2; i++)
#pragma unroll
        for (int j = 0; j < 4; j++)
#pragma unroll
            for (int q = 0; q < 4; q++) acc[i][j][q] = 0.f;

    const int marow = m0 + lrow, mclamp = marow < S_ ? marow : S_ - 1;
    const int narow = n0 + lrow, nclamp = narow < S_ ? narow : S_ - 1;
    uint4 ra0, ra1, rb0, rb1;
    auto gload = [&](int c) {
        const int seg = c / 6;
        const int k0 = (c - seg * 6) * 32 + lcol;
        const __nv_bfloat16* A = (seg == 1) ? g_q_lo : g_q_hi;
        const __nv_bfloat16* B = (seg == 2) ? g_k_lo : g_k_hi;
        const __nv_bfloat16* ap = A + (size_t)(b * S_ + mclamp) * E_ + h * HD_ + k0;
        const __nv_bfloat16* bp = B + (size_t)(b * S_ + nclamp) * E_ + h * HD_ + k0;
        ra0 = *(const uint4*)ap; ra1 = *(const uint4*)(ap + 8);
        rb0 = *(const uint4*)bp; rb1 = *(const uint4*)(bp + 8);
    };
    auto sstore = [&](int st) {
        *(uint4*)&As[st][lrow][lcol] = ra0; *(uint4*)&As[st][lrow][lcol + 8] = ra1;
        *(uint4*)&Bs[st][lrow][lcol] = rb0; *(uint4*)&Bs[st][lrow][lcol + 8] = rb1;
    };

    const uint32_t aBase = smem_u32(&As[0][0][0]);
    const uint32_t bBase = smem_u32(&Bs[0][0][0]);
    const int arow = wm + (lane & 15);
    const int akoff = (lane >> 4) * 8;
    const int brow = wn + (lane & 7);
    const int bkoff = ((lane >> 3) & 1) * 8;

    gload(0); sstore(0);
    __syncthreads();
    for (int c = 0; c < 18; c++) {
        const int st = c & 1;
        if (c + 1 < 18) gload(c + 1);
        const uint32_t aS = aBase + st * SC_STG * 2;
        const uint32_t bS = bBase + st * SC_STG * 2;
#pragma unroll
        for (int ks = 0; ks < 2; ks++) {
            const int k = ks * 16;
            uint32_t af[2][4], bf[4][2];
#pragma unroll
            for (int mt = 0; mt < 2; mt++)
                ldsm_x4(af[mt], aS + ((arow + mt * 16) * SSTR + k + akoff) * 2);
#pragma unroll
            for (int nt = 0; nt < 4; nt++)
                ldsm_x2(bf[nt], bS + ((brow + nt * 8) * SSTR + k + bkoff) * 2);
#pragma unroll
            for (int mt = 0; mt < 2; mt++)
#pragma unroll
                for (int nt = 0; nt < 4; nt++)
                    mma16816(acc[mt][nt], af[mt], bf[nt]);
        }
        if (c + 1 < 18) sstore(st ^ 1);
        __syncthreads();
    }

    const float scale = rsqrtf((float)HD_);
    const int erow = lane >> 2, ecol = (lane & 3) * 2;
    float* Sp = g_scores + (size_t)bh * S_ * SKP;
#pragma unroll
    for (int mt = 0; mt < 2; mt++) {
#pragma unroll
        for (int nt = 0; nt < 4; nt++) {
            const int col = n0 + wn + nt * 8 + ecol;
            if (col >= S_) continue;
            const int r0 = m0 + wm + mt * 16 + erow;
            if (r0 < S_)
                *(float2*)&Sp[(size_t)r0 * SKP + col] =
                    make_float2(acc[mt][nt][0] * scale, acc[mt][nt][1] * scale);
            if (r0 + 8 < S_)
                *(float2*)&Sp[(size_t)(r0 + 8) * SKP + col] =
                    make_float2(acc[mt][nt][2] * scale, acc[mt][nt][3] * scale);
        }
    }
}

// ============================================================================
// Softmax rows -> bf16 hi/lo probs (224 cols, zero pad)
// ============================================================================
__global__ __launch_bounds__(256) void softmax_rows()
{
    const int row = (blockIdx.x * blockDim.x + threadIdx.x) >> 5;
    const int lane = threadIdx.x & 31;
    if (row >= NBH * S_) return;
    const float* p = g_scores + (size_t)row * SKP;
    float v[7];
    float mx = -1e30f;
#pragma unroll
    for (int i = 0; i < 7; i++) {
        int j = lane + i * 32;
        v[i] = (j < S_) ? p[j] : -1e30f;
        mx = fmaxf(mx, v[i]);
    }
#pragma unroll
    for (int o = 16; o > 0; o >>= 1) mx = fmaxf(mx, __shfl_xor_sync(0xFFFFFFFFu, mx, o));
    float sum = 0.f;
#pragma unroll
    for (int i = 0; i < 7; i++) {
        int j = lane + i * 32;
        v[i] = (j < S_) ? __expf(v[i] - mx) : 0.f;
        sum += v[i];
    }
#pragma unroll
    for (int o = 16; o > 0; o >>= 1) sum += __shfl_xor_sync(0xFFFFFFFFu, sum, o);
    const float inv = 1.0f / sum;
    __nv_bfloat16* ah = g_at_hi + (size_t)row * SKP;
    __nv_bfloat16* al = g_at_lo + (size_t)row * SKP;
#pragma unroll
    for (int i = 0; i < 7; i++) {
        int j = lane + i * 32;
        float val = (j < S_) ? v[i] * inv : 0.f;
        __nv_bfloat16 hi, lo;
        split1(val, hi, lo);
        ah[j] = hi; al[j] = lo;
    }
}

__global__ __launch_bounds__(256) void vt_zero()
{
    const int gid = blockIdx.x * 256 + threadIdx.x;
    const int total = NBH * HD_ * (SKP - S_);
    if (gid >= total) return;
    const int row = gid / (SKP - S_);
    const int s = S_ + gid - row * (SKP - S_);
    g_vt_hi[(size_t)row * SKP + s] = __float2bfloat16(0.f);
    g_vt_lo[(size_t)row * SKP + s] = __float2bfloat16(0.f);
}

// ============================================================================
// AV via HMMA
// ============================================================================
__global__ __launch_bounds__(128) void av_mma()
{
    __shared__ __nv_bfloat16 As[2][64][SSTR];
    __shared__ __nv_bfloat16 Bs[2][64][SSTR];
    const int bh = blockIdx.z;
    const int b = bh >> 2, h = bh & 3;
    const int tid = threadIdx.x;
    const int wid = tid >> 5, lane = tid & 31;
    const int m0 = blockIdx.y * 64, n0 = blockIdx.x * 64;
    const int wm = (wid >> 1) * 32, wn = (wid & 1) * 32;
    const int lrow = tid >> 1, lcol = (tid & 1) * 16;

    float acc[2][4][4];
#pragma unroll
    for (int i = 0; i < 2; i++)
#pragma unroll
        for (int j = 0; j < 4; j++)
#pragma unroll
            for (int q = 0; q < 4; q++) acc[i][j][q] = 0.f;

    const int marow = m0 + lrow, mclamp = marow < S_ ? marow : S_ - 1;
    uint4 ra0, ra1, rb0, rb1;
    auto gload = [&](int c) {
        const int seg = c / 7;
        const int k0 = (c - seg * 7) * 32 + lcol;
        const __nv_bfloat16* A = (seg == 1) ? g_at_lo : g_at_hi;
        const __nv_bfloat16* B = (seg == 2) ? g_vt_lo : g_vt_hi;
        const __nv_bfloat16* ap = A + ((size_t)bh * S_ + mclamp) * SKP + k0;
        const __nv_bfloat16* bp = B + ((size_t)bh * HD_ + n0 + lrow) * SKP + k0;
        ra0 = *(const uint4*)ap; ra1 = *(const uint4*)(ap + 8);
        rb0 = *(const uint4*)bp; rb1 = *(const uint4*)(bp + 8);
    };
    auto sstore = [&](int st) {
        *(uint4*)&As[st][lrow][lcol] = ra0; *(uint4*)&As[st][lrow][lcol + 8] = ra1;
        *(uint4*)&Bs[st][lrow][lcol] = rb0; *(uint4*)&Bs[st][lrow][lcol + 8] = rb1;
    };

    const uint32_t aBase = smem_u32(&As[0][0][0]);
    const uint32_t bBase = smem_u32(&Bs[0][0][0]);
    const int arow = wm + (lane & 15);
    const int akoff = (lane >> 4) * 8;
    const int brow = wn + (lane & 7);
    const int bkoff = ((lane >> 3) & 1) * 8;

    gload(0); sstore(0);
    __syncthreads();
    for (int c = 0; c < 21; c++) {
        const int st = c & 1;
        if (c + 1 < 21) gload(c + 1);
        const uint32_t aS = aBase + st * SC_STG * 2;
        const uint32_t bS = bBase + st * SC_STG * 2;
#pragma unroll
        for (int ks = 0; ks < 2; ks++) {
            const int k = ks * 16;
            uint32_t af[2][4], bf[4][2];
#pragma unroll
            for (int mt = 0; mt < 2; mt++)
                ldsm_x4(af[mt], aS + ((arow + mt * 16) * SSTR + k + akoff) * 2);
#pragma unroll
            for (int nt = 0; nt < 4; nt++)
                ldsm_x2(bf[nt], bS + ((brow + nt * 8) * SSTR + k + bkoff) * 2);
#pragma unroll
            for (int mt = 0; mt < 2; mt++)
#pragma unroll
                for (int nt = 0; nt < 4; nt++)
                    mma16816(acc[mt][nt], af[mt], bf[nt]);
        }
        if (c + 1 < 21) sstore(st ^ 1);
        __syncthreads();
    }

    const int erow = lane >> 2, ecol = (lane & 3) * 2;
#pragma unroll
    for (int mt = 0; mt < 2; mt++) {
#pragma unroll
        for (int nt = 0; nt < 4; nt++) {
            const int col = n0 + wn + nt * 8 + ecol;
            const int r0 = m0 + wm + mt * 16 + erow;
#pragma unroll
            for (int rr = 0; rr < 2; rr++) {
                const int r = r0 + rr * 8;
                if (r >= S_) continue;
                const float va = acc[mt][nt][rr * 2 + 0];
                const float vb = acc[mt][nt][rr * 2 + 1];
                __nv_bfloat16 h0, l0, h1, l1;
                split1(va, h0, l0); split1(vb, h1, l1);
                const size_t off = ((size_t)(b * S_ + r)) * E_ + h * HD_ + col;
                *(__nv_bfloat162*)&g_o_hi[off] = __nv_bfloat162(h0, h1);
                *(__nv_bfloat162*)&g_o_lo[off] = __nv_bfloat162(l0, l1);
            }
        }
    }
}

// ============================================================================
// Splits
// ============================================================================
__global__ __launch_bounds__(256) void weight_split(
    const float* __restrict__ w, __nv_bfloat16* __restrict__ hi,
    __nv_bfloat16* __restrict__ lo)
{
    const int gid = blockIdx.x * 256 + threadIdx.x;
    if (gid >= WN_ / 4) return;
    float4 v = *(const float4*)(w + gid * 4);
    __nv_bfloat16 h0, l0;
#pragma unroll
    for (int i = 0; i < 4; i++) {
        split1((&v.x)[i], h0, l0);
        hi[gid * 4 + i] = h0;
        lo[gid * 4 + i] = l0;
    }
}

__global__ __launch_bounds__(256) void patch_split(
    const float* __restrict__ x, __nv_bfloat16* __restrict__ hi,
    __nv_bfloat16* __restrict__ lo)
{
    const int gid = blockIdx.x * 256 + threadIdx.x;
    if (gid >= NE_ / 4) return;
    const int m = gid / 192;
    const int k = (gid - m * 192) * 4;
    const int b = m / S_;
    const int s = m - b * S_;
    const int gy = s / 14, gx = s - gy * 14;
    const int c = k >> 8;
    const int py = (k >> 4) & 15;
    const int px = k & 15;
    const float* src = x + ((((size_t)b * 3 + c) * 224 + gy * 16 + py) * 224 + gx * 16 + px);
    float4 v = *(const float4*)src;
    const size_t o = (size_t)m * E_ + k;
    __nv_bfloat16 h0, l0;
#pragma unroll
    for (int i = 0; i < 4; i++) {
        split1((&v.x)[i], h0, l0);
        hi[o + i] = h0;
        lo[o + i] = l0;
    }
}

// ============================================================================
// LayerNorm over [S,E] per batch
// ============================================================================
__global__ __launch_bounds__(256) void ln_partial(
    const float* __restrict__ A, const float* __restrict__ R)
{
    const int b = blockIdx.x, chunk = blockIdx.y;
    const size_t base = (size_t)b * LN_N + (size_t)chunk * LN_CH;
    float s = 0.f, sq = 0.f;
    for (int i = threadIdx.x; i < LN_CH; i += 256) {
        float v = A[base + i];
        if (R) v += R[base + i];
        s += v; sq += v * v;
    }
    __shared__ float ss[256], sb[256];
    ss[threadIdx.x] = s; sb[threadIdx.x] = sq;
    __syncthreads();
    for (int o = 128; o > 0; o >>= 1) {
        if (threadIdx.x < o) {
            ss[threadIdx.x] += ss[threadIdx.x + o];
            sb[threadIdx.x] += sb[threadIdx.x + o];
        }
        __syncthreads();
    }
    if (threadIdx.x == 0) {
        g_psum[b * LN_CHUNKS + chunk] = ss[0];
        g_psq [b * LN_CHUNKS + chunk] = sb[0];
    }
}

__global__ void ln_finalize()
{
    const int b = threadIdx.x;
    if (b >= B_) return;
    float s = 0.f, sq = 0.f;
#pragma unroll
    for (int i = 0; i < LN_CHUNKS; i++) {
        s  += g_psum[b * LN_CHUNKS + i];
        sq += g_psq [b * LN_CHUNKS + i];
    }
    const float inv_n = 1.0f / (float)LN_N;
    float mu = s * inv_n;
    float var = sq * inv_n - mu * mu;
    g_mu[b] = mu;
    g_rstd[b] = rsqrtf(var + 1e-5f);
}

__global__ __launch_bounds__(256) void ln_apply_split(
    const float* __restrict__ A, const float* __restrict__ w,
    const float* __restrict__ bias)
{
    const int gid = blockIdx.x * 256 + threadIdx.x;
    if (gid >= NE_) return;
    const int b = gid / LN_N;
    const int r = gid - b * LN_N;
    float v = (A[gid] - g_mu[b]) * g_rstd[b] * w[r] + bias[r];
    __nv_bfloat16 hi, lo;
    split1(v, hi, lo);
    g_h_hi[gid] = hi;
    g_h_lo[gid] = lo;
}

__global__ __launch_bounds__(256) void ln_apply(
    const float* __restrict__ A, const float* __restrict__ R,
    const float* __restrict__ w, const float* __restrict__ bias,
    float* __restrict__ out)
{
    const int gid = blockIdx.x * 256 + threadIdx.x;
    if (gid >= NE_) return;
    const int b = gid / LN_N;
    const int r = gid - b * LN_N;
    float v = A[gid] + R[gid];
    out[gid] = (v - g_mu[b]) * g_rstd[b] * w[r] + bias[r];
}

// ============================================================================
// Launch
// ============================================================================
extern "C" void kernel_launch(void* const* d_in, const int* in_sizes, int n_in,
                              void* d_out, int out_size)
{
    const float* x      = (const float*)d_in[0];
    const float* conv_w = (const float*)d_in[1];
    const float* conv_b = (const float*)d_in[2];
    const float* wq = (const float*)d_in[3];  const float* bq = (const float*)d_in[4];
    const float* wk = (const float*)d_in[5];  const float* bk = (const float*)d_in[6];
    const float* wv = (const float*)d_in[7];  const float* bv = (const float*)d_in[8];
    const float* wo = (const float*)d_in[9];  const float* bo = (const float*)d_in[10];
    const float* ln1w = (const float*)d_in[11]; const float* ln1b = (const float*)d_in[12];
    const float* ln2w = (const float*)d_in[13]; const float* ln2b = (const float*)d_in[14];
    float* out = (float*)d_out;

    float *emb, *op;
    cudaGetSymbolAddress((void**)&emb, g_emb);
    cudaGetSymbolAddress((void**)&op,  g_op);
    __nv_bfloat16 *aph, *apl, *hh, *hl, *qh, *ql, *kh, *kl, *vth, *vtl, *oh, *ol, *wh, *wl;
    cudaGetSymbolAddress((void**)&aph, g_ap_hi);
    cudaGetSymbolAddress((void**)&apl, g_ap_lo);
    cudaGetSymbolAddress((void**)&hh,  g_h_hi);
    cudaGetSymbolAddress((void**)&hl,  g_h_lo);
    cudaGetSymbolAddress((void**)&qh,  g_q_hi);
    cudaGetSymbolAddress((void**)&ql,  g_q_lo);
    cudaGetSymbolAddress((void**)&kh,  g_k_hi);
    cudaGetSymbolAddress((void**)&kl,  g_k_lo);
    cudaGetSymbolAddress((void**)&vth, g_vt_hi);
    cudaGetSymbolAddress((void**)&vtl, g_vt_lo);
    cudaGetSymbolAddress((void**)&oh,  g_o_hi);
    cudaGetSymbolAddress((void**)&ol,  g_o_lo);
    cudaGetSymbolAddress((void**)&wh,  g_w_hi);
    cudaGetSymbolAddress((void**)&wl,  g_w_lo);

    cudaFuncSetAttribute(gemm_mma, cudaFuncAttributeMaxDynamicSharedMemorySize, GEMM_SMEM);

    const dim3 gemm_grid(6, 49);           // 256x128 tiles
    const dim3 sc_grid(4, 4, NBH);
    const dim3 av_grid(3, 4, NBH);
    const dim3 lnp_grid(B_, LN_CHUNKS);
    const int  lna_blocks = NE_ / 256;
    const int  sm_blocks = (NBH * S_ * 32 + 255) / 256;
    const int  ws_blocks = (WN_ / 4 + 255) / 256;
    const int  ps_blocks = (NE_ / 4 + 255) / 256;
    const int  vz_blocks = (NBH * HD_ * (SKP - S_) + 255) / 256;

    // 0. splits
    weight_split<<<ws_blocks, 256>>>(conv_w, wh + 0 * (size_t)WN_, wl + 0 * (size_t)WN_);
    weight_split<<<ws_blocks, 256>>>(wq,     wh + 1 * (size_t)WN_, wl + 1 * (size_t)WN_);
    weight_split<<<ws_blocks, 256>>>(wk,     wh + 2 * (size_t)WN_, wl + 2 * (size_t)WN_);
    weight_split<<<ws_blocks, 256>>>(wv,     wh + 3 * (size_t)WN_, wl + 3 * (size_t)WN_);
    weight_split<<<ws_blocks, 256>>>(wo,     wh + 4 * (size_t)WN_, wl + 4 * (size_t)WN_);
    patch_split<<<ps_blocks, 256>>>(x, aph, apl);
    vt_zero<<<vz_blocks, 256>>>();
    // 1. patch embedding -> emb (fp32)
    gemm_mma<<<gemm_grid, 256, GEMM_SMEM>>>(
        aph, apl, wh + 0 * (size_t)WN_, wl + 0 * (size_t)WN_, conv_b, emb, nullptr, nullptr, 0);
    // 2. LN1 -> h hi/lo
    ln_partial<<<lnp_grid, 256>>>(emb, nullptr);
    ln_finalize<<<1, 64>>>();
    ln_apply_split<<<lna_blocks, 256>>>(emb, ln1w, ln1b);
    // 3. QKV
    gemm_mma<<<gemm_grid, 256, GEMM_SMEM>>>(
        hh, hl, wh + 1 * (size_t)WN_, wl + 1 * (size_t)WN_, bq, nullptr, qh, ql, 1);
    gemm_mma<<<gemm_grid, 256, GEMM_SMEM>>>(
        hh, hl, wh + 2 * (size_t)WN_, wl + 2 * (size_t)WN_, bk, nullptr, kh, kl, 1);
    gemm_mma<<<gemm_grid, 256, GEMM_SMEM>>>(
        hh, hl, wh + 3 * (size_t)WN_, wl + 3 * (size_t)WN_, bv, nullptr, vth, vtl, 2);
    // 4. attention
    scores_mma<<<sc_grid, 128>>>();
    softmax_rows<<<sm_blocks, 256>>>();
    av_mma<<<av_grid, 128>>>();
    // 5. output projection -> op (fp32)
    gemm_mma<<<gemm_grid, 256, GEMM_SMEM>>>(
        oh, ol, wh + 4 * (size_t)WN_, wl + 4 * (size_t)WN_, bo, op, nullptr, nullptr, 0);
    // 6. residual + LN2 -> out
    ln_partial<<<lnp_grid, 256>>>(emb, op);
    ln_finalize<<<1, 64>>>();
    ln_apply<<<lna_blocks, 256>>>(emb, op, ln2w, ln2b, out);
}

// round 6
// speedup vs baseline: 2.3352x; 1.0369x over previous
#include <cuda_runtime.h>
#include <cuda_bf16.h>
#include <math.h>
#include <stdint.h>

// Problem constants
#define B_   64
#define S_   196
#define E_   768
#define H_   4
#define HD_  192
#define M_   (B_*S_)        // 12544
#define NE_  (B_*S_*E_)     // 9,633,792
#define LN_N (S_*E_)        // 150,528
#define LN_CHUNKS 8
#define LN_CH (LN_N/LN_CHUNKS)
#define WN_  (E_*E_)
#define SKP  224            // padded seq
#define NBH  (B_*H_)        // 256

// ---------------- scratch (device globals) ----------------
__device__ __align__(256) float g_emb[NE_];
__device__ __align__(256) float g_op[NE_];
__device__ __align__(256) float g_scores[NBH*S_*SKP];
__device__ float g_psum[B_*LN_CHUNKS];
__device__ float g_psq[B_*LN_CHUNKS];
__device__ float g_mu[B_];
__device__ float g_rstd[B_];

__device__ __align__(256) __nv_bfloat16 g_ap_hi[NE_];
__device__ __align__(256) __nv_bfloat16 g_ap_lo[NE_];
__device__ __align__(256) __nv_bfloat16 g_h_hi[NE_];
__device__ __align__(256) __nv_bfloat16 g_h_lo[NE_];
__device__ __align__(256) __nv_bfloat16 g_q_hi[NE_];
__device__ __align__(256) __nv_bfloat16 g_q_lo[NE_];
__device__ __align__(256) __nv_bfloat16 g_k_hi[NE_];
__device__ __align__(256) __nv_bfloat16 g_k_lo[NE_];
__device__ __align__(256) __nv_bfloat16 g_vt_hi[NBH*HD_*SKP];
__device__ __align__(256) __nv_bfloat16 g_vt_lo[NBH*HD_*SKP];
__device__ __align__(256) __nv_bfloat16 g_at_hi[NBH*S_*SKP];
__device__ __align__(256) __nv_bfloat16 g_at_lo[NBH*S_*SKP];
__device__ __align__(256) __nv_bfloat16 g_o_hi[NE_];
__device__ __align__(256) __nv_bfloat16 g_o_lo[NE_];
__device__ __align__(256) __nv_bfloat16 g_w_hi[5][WN_];
__device__ __align__(256) __nv_bfloat16 g_w_lo[5][WN_];

// ============================================================================
// PTX helpers
// ============================================================================
__device__ __forceinline__ uint32_t smem_u32(const void* p) {
    uint32_t a;
    asm("{ .reg .u64 t; cvta.to.shared.u64 t, %1; cvt.u32.u64 %0, t; }"
        : "=r"(a) : "l"(p));
    return a;
}
__device__ __forceinline__ void ldsm_x4(uint32_t* r, uint32_t addr) {
    asm volatile("ldmatrix.sync.aligned.m8n8.x4.shared.b16 {%0,%1,%2,%3}, [%4];"
                 : "=r"(r[0]), "=r"(r[1]), "=r"(r[2]), "=r"(r[3]) : "r"(addr));
}
__device__ __forceinline__ void ldsm_x2(uint32_t* r, uint32_t addr) {
    asm volatile("ldmatrix.sync.aligned.m8n8.x2.shared.b16 {%0,%1}, [%2];"
                 : "=r"(r[0]), "=r"(r[1]) : "r"(addr));
}
__device__ __forceinline__ void mma16816(float* c, const uint32_t* a, const uint32_t* b) {
    asm volatile(
        "mma.sync.aligned.m16n8k16.row.col.f32.bf16.bf16.f32 "
        "{%0,%1,%2,%3}, {%4,%5,%6,%7}, {%8,%9}, {%0,%1,%2,%3};"
        : "+f"(c[0]), "+f"(c[1]), "+f"(c[2]), "+f"(c[3])
        : "r"(a[0]), "r"(a[1]), "r"(a[2]), "r"(a[3]), "r"(b[0]), "r"(b[1]));
}
__device__ __forceinline__ void cp16(uint32_t saddr, const void* gaddr) {
    asm volatile("cp.async.cg.shared.global [%0], [%1], 16;"
                 :: "r"(saddr), "l"(gaddr) : "memory");
}
#define CP_COMMIT() asm volatile("cp.async.commit_group;" ::: "memory")
#define CP_WAIT1()  asm volatile("cp.async.wait_group 1;" ::: "memory")

__device__ __forceinline__ void split1(float x, __nv_bfloat16& hi, __nv_bfloat16& lo) {
    hi = __float2bfloat16(x);
    lo = __float2bfloat16(x - __bfloat162float(hi));
}

// ============================================================================
// HMMA bf16-split GEMM, cp.async 3-stage pipeline.
// CTA 256x128, K-stage 64, 36 chunks (3 terms x 12). 8 warps, warp tile 64x64.
// mode 0: fp32 C.  mode 1: split hi/lo.  mode 2: split + per-head transpose (V).
// ============================================================================
#define ASTR 72
#define ROWB 144
#define A_STG (256 * ROWB)
#define B_STG (128 * ROWB)
#define STG_BYTES (A_STG + B_STG)
#define GEMM_SMEM (3 * STG_BYTES)

__global__ __launch_bounds__(256, 1) void gemm_mma(
    const __nv_bfloat16* __restrict__ Ahi, const __nv_bfloat16* __restrict__ Alo,
    const __nv_bfloat16* __restrict__ Bhi, const __nv_bfloat16* __restrict__ Blo,
    const float* __restrict__ bias, float* __restrict__ C,
    __nv_bfloat16* __restrict__ Chi, __nv_bfloat16* __restrict__ Clo, int mode)
{
    extern __shared__ char smem[];
    const uint32_t sbase = smem_u32(smem);
    const int tid = threadIdx.x;
    const int wid = tid >> 5, lane = tid & 31;
    const int m0 = blockIdx.y * 256, n0 = blockIdx.x * 128;
    const int wm = (wid >> 1) * 64, wn = (wid & 1) * 64;
    const int lr = tid >> 3, lseg = tid & 7;

    float acc[4][8][4];
#pragma unroll
    for (int i = 0; i < 4; i++)
#pragma unroll
        for (int j = 0; j < 8; j++)
#pragma unroll
            for (int q = 0; q < 4; q++) acc[i][j][q] = 0.f;

    auto issue = [&](int c, int st) {
        const int term = c / 12;
        const int k0 = (c - term * 12) * 64 + lseg * 8;
        const __nv_bfloat16* A = (term == 1) ? Alo : Ahi;
        const __nv_bfloat16* B = (term == 2) ? Blo : Bhi;
        const uint32_t base = sbase + st * STG_BYTES;
#pragma unroll
        for (int i = 0; i < 8; i++) {
            const int row = i * 32 + lr;
            cp16(base + row * ROWB + lseg * 16,
                 A + (size_t)(m0 + row) * E_ + k0);
        }
#pragma unroll
        for (int i = 0; i < 4; i++) {
            const int row = i * 32 + lr;
            cp16(base + A_STG + row * ROWB + lseg * 16,
                 B + (size_t)(n0 + row) * E_ + k0);
        }
    };

    const int arow = wm + (lane & 15);
    const int akoff = (lane >> 4) * 8;
    const int brow = wn + (lane & 7) + ((lane >> 4) << 3);
    const int bkoff = ((lane >> 3) & 1) * 8;

    issue(0, 0); CP_COMMIT();
    issue(1, 1); CP_COMMIT();

    for (int c = 0; c < 36; c++) {
        const int st = c - (c / 3) * 3;
        CP_WAIT1();
        __syncthreads();
        if (c + 2 < 36) {
            int ns = c + 2; ns -= (ns / 3) * 3;
            issue(c + 2, ns);
        }
        CP_COMMIT();
        const uint32_t aStage = sbase + st * STG_BYTES;
        const uint32_t bStage = aStage + A_STG;
#pragma unroll
        for (int ks = 0; ks < 4; ks++) {
            const int k = ks * 16;
            uint32_t af[4][4], bf[4][4];
#pragma unroll
            for (int mt = 0; mt < 4; mt++)
                ldsm_x4(af[mt], aStage + ((arow + mt * 16) * ASTR + k + akoff) * 2);
#pragma unroll
            for (int nt2 = 0; nt2 < 4; nt2++)
                ldsm_x4(bf[nt2], bStage + ((brow + nt2 * 16) * ASTR + k + bkoff) * 2);
#pragma unroll
            for (int mt = 0; mt < 4; mt++)
#pragma unroll
                for (int nt = 0; nt < 8; nt++)
                    mma16816(acc[mt][nt], af[mt], &bf[nt >> 1][(nt & 1) * 2]);
        }
    }

    const int erow = lane >> 2;
    const int ecol = (lane & 3) * 2;
#pragma unroll
    for (int mt = 0; mt < 4; mt++) {
#pragma unroll
        for (int nt = 0; nt < 8; nt++) {
            const int col = n0 + wn + nt * 8 + ecol;
            const float b0 = bias[col], b1 = bias[col + 1];
            const int r0 = m0 + wm + mt * 16 + erow;
            float v00 = acc[mt][nt][0] + b0, v01 = acc[mt][nt][1] + b1;
            float v10 = acc[mt][nt][2] + b0, v11 = acc[mt][nt][3] + b1;
            if (mode == 0) {
                *(float2*)&C[(size_t)r0 * E_ + col] = make_float2(v00, v01);
                *(float2*)&C[(size_t)(r0 + 8) * E_ + col] = make_float2(v10, v11);
            } else if (mode == 1) {
                __nv_bfloat16 h0, l0, h1, l1;
                split1(v00, h0, l0); split1(v01, h1, l1);
                size_t off = (size_t)r0 * E_ + col;
                *(__nv_bfloat162*)&Chi[off] = __nv_bfloat162(h0, h1);
                *(__nv_bfloat162*)&Clo[off] = __nv_bfloat162(l0, l1);
                split1(v10, h0, l0); split1(v11, h1, l1);
                off = (size_t)(r0 + 8) * E_ + col;
                *(__nv_bfloat162*)&Chi[off] = __nv_bfloat162(h0, h1);
                *(__nv_bfloat162*)&Clo[off] = __nv_bfloat162(l0, l1);
            } else {
                const int hh = col / HD_, d = col - hh * HD_;
#pragma unroll
                for (int rr = 0; rr < 2; rr++) {
                    const int r = r0 + rr * 8;
                    const int bb = r / S_, s = r - bb * S_;
                    const float va = rr ? v10 : v00;
                    const float vb = rr ? v11 : v01;
                    __nv_bfloat16 h0, l0;
                    size_t o0 = ((size_t)(bb * H_ + hh) * HD_ + d) * SKP + s;
                    split1(va, h0, l0); Chi[o0] = h0; Clo[o0] = l0;
                    split1(vb, h0, l0); Chi[o0 + SKP] = h0; Clo[o0 + SKP] = l0;
                }
            }
        }
    }
}

// ============================================================================
// Attention scores via HMMA: 256 threads, CTA tile 128x128, warp tile 64x32.
// K = 3 terms x 192 -> 18 chunks of 32.
// ============================================================================
#define SSTR 40

__global__ __launch_bounds__(256) void scores_mma()
{
    __shared__ __nv_bfloat16 As[2][128][SSTR];
    __shared__ __nv_bfloat16 Bs[2][128][SSTR];
    const int bh = blockIdx.z;
    const int b = bh >> 2, h = bh & 3;
    const int tid = threadIdx.x;
    const int wid = tid >> 5, lane = tid & 31;
    const int m0 = blockIdx.y * 128, n0 = blockIdx.x * 128;
    const int wm = (wid >> 2) * 64, wn = (wid & 3) * 32;
    const int lrow = tid >> 1, lcol = (tid & 1) * 16;

    float acc[4][4][4];
#pragma unroll
    for (int i = 0; i < 4; i++)
#pragma unroll
        for (int j = 0; j < 4; j++)
#pragma unroll
            for (int q = 0; q < 4; q++) acc[i][j][q] = 0.f;

    const int mrow = m0 + lrow, mclamp = mrow < S_ ? mrow : S_ - 1;
    const int nrow = n0 + lrow, nclamp = nrow < S_ ? nrow : S_ - 1;
    uint4 ra0, ra1, rb0, rb1;
    auto gload = [&](int c) {
        const int seg = c / 6;
        const int k0 = (c - seg * 6) * 32 + lcol;
        const __nv_bfloat16* A = (seg == 1) ? g_q_lo : g_q_hi;
        const __nv_bfloat16* B = (seg == 2) ? g_k_lo : g_k_hi;
        const __nv_bfloat16* ap = A + (size_t)(b * S_ + mclamp) * E_ + h * HD_ + k0;
        const __nv_bfloat16* bp = B + (size_t)(b * S_ + nclamp) * E_ + h * HD_ + k0;
        ra0 = *(const uint4*)ap; ra1 = *(const uint4*)(ap + 8);
        rb0 = *(const uint4*)bp; rb1 = *(const uint4*)(bp + 8);
    };
    auto sstore = [&](int st) {
        *(uint4*)&As[st][lrow][lcol] = ra0; *(uint4*)&As[st][lrow][lcol + 8] = ra1;
        *(uint4*)&Bs[st][lrow][lcol] = rb0; *(uint4*)&Bs[st][lrow][lcol + 8] = rb1;
    };

    const uint32_t aBase = smem_u32(&As[0][0][0]);
    const uint32_t bBase = smem_u32(&Bs[0][0][0]);
    const int arow = wm + (lane & 15);
    const int akoff = (lane >> 4) * 8;
    const int brow = wn + (lane & 7);
    const int bkoff = ((lane >> 3) & 1) * 8;

    gload(0); sstore(0);
    __syncthreads();
    for (int c = 0; c < 18; c++) {
        const int st = c & 1;
        if (c + 1 < 18) gload(c + 1);
        const uint32_t aS = aBase + st * (128 * SSTR * 2);
        const uint32_t bS = bBase + st * (128 * SSTR * 2);
#pragma unroll
        for (int ks = 0; ks < 2; ks++) {
            const int k = ks * 16;
            uint32_t af[4][4], bf[4][2];
#pragma unroll
            for (int mt = 0; mt < 4; mt++)
                ldsm_x4(af[mt], aS + ((arow + mt * 16) * SSTR + k + akoff) * 2);
#pragma unroll
            for (int nt = 0; nt < 4; nt++)
                ldsm_x2(bf[nt], bS + ((brow + nt * 8) * SSTR + k + bkoff) * 2);
#pragma unroll
            for (int mt = 0; mt < 4; mt++)
#pragma unroll
                for (int nt = 0; nt < 4; nt++)
                    mma16816(acc[mt][nt], af[mt], bf[nt]);
        }
        if (c + 1 < 18) sstore(st ^ 1);
        __syncthreads();
    }

    const float scale = rsqrtf((float)HD_);
    const int erow = lane >> 2, ecol = (lane & 3) * 2;
    float* Sp = g_scores + (size_t)bh * S_ * SKP;
#pragma unroll
    for (int mt = 0; mt < 4; mt++) {
#pragma unroll
        for (int nt = 0; nt < 4; nt++) {
            const int col = n0 + wn + nt * 8 + ecol;
            if (col >= S_) continue;
            const int r0 = m0 + wm + mt * 16 + erow;
            if (r0 < S_)
                *(float2*)&Sp[(size_t)r0 * SKP + col] =
                    make_float2(acc[mt][nt][0] * scale, acc[mt][nt][1] * scale);
            if (r0 + 8 < S_)
                *(float2*)&Sp[(size_t)(r0 + 8) * SKP + col] =
                    make_float2(acc[mt][nt][2] * scale, acc[mt][nt][3] * scale);
        }
    }
}

// ============================================================================
// Softmax rows -> bf16 hi/lo probs (224 cols, zero pad)
// ============================================================================
__global__ __launch_bounds__(256) void softmax_rows()
{
    const int row = (blockIdx.x * blockDim.x + threadIdx.x) >> 5;
    const int lane = threadIdx.x & 31;
    if (row >= NBH * S_) return;
    const float* p = g_scores + (size_t)row * SKP;
    float v[7];
    float mx = -1e30f;
#pragma unroll
    for (int i = 0; i < 7; i++) {
        int j = lane + i * 32;
        v[i] = (j < S_) ? p[j] : -1e30f;
        mx = fmaxf(mx, v[i]);
    }
#pragma unroll
    for (int o = 16; o > 0; o >>= 1) mx = fmaxf(mx, __shfl_xor_sync(0xFFFFFFFFu, mx, o));
    float sum = 0.f;
#pragma unroll
    for (int i = 0; i < 7; i++) {
        int j = lane + i * 32;
        v[i] = (j < S_) ? __expf(v[i] - mx) : 0.f;
        sum += v[i];
    }
#pragma unroll
    for (int o = 16; o > 0; o >>= 1) sum += __shfl_xor_sync(0xFFFFFFFFu, sum, o);
    const float inv = 1.0f / sum;
    __nv_bfloat16* ah = g_at_hi + (size_t)row * SKP;
    __nv_bfloat16* al = g_at_lo + (size_t)row * SKP;
#pragma unroll
    for (int i = 0; i < 7; i++) {
        int j = lane + i * 32;
        float val = (j < S_) ? v[i] * inv : 0.f;
        __nv_bfloat16 hi, lo;
        split1(val, hi, lo);
        ah[j] = hi; al[j] = lo;
    }
}

__global__ __launch_bounds__(256) void vt_zero()
{
    const int gid = blockIdx.x * 256 + threadIdx.x;
    const int total = NBH * HD_ * (SKP - S_);
    if (gid >= total) return;
    const int row = gid / (SKP - S_);
    const int s = S_ + gid - row * (SKP - S_);
    g_vt_hi[(size_t)row * SKP + s] = __float2bfloat16(0.f);
    g_vt_lo[(size_t)row * SKP + s] = __float2bfloat16(0.f);
}

// ============================================================================
// AV via HMMA: 256 threads, CTA tile 128x64, warp tile 32x32.
// K = 3 terms x 224 -> 21 chunks of 32.
// ============================================================================
__global__ __launch_bounds__(256) void av_mma()
{
    __shared__ __nv_bfloat16 As[2][128][SSTR];
    __shared__ __nv_bfloat16 Bs[2][64][SSTR];
    const int bh = blockIdx.z;
    const int b = bh >> 2, h = bh & 3;
    const int tid = threadIdx.x;
    const int wid = tid >> 5, lane = tid & 31;
    const int m0 = blockIdx.y * 128, n0 = blockIdx.x * 64;
    const int wm = (wid >> 1) * 32, wn = (wid & 1) * 32;
    const int lrow = tid >> 1, lcol = (tid & 1) * 16;

    float acc[2][4][4];
#pragma unroll
    for (int i = 0; i < 2; i++)
#pragma unroll
        for (int j = 0; j < 4; j++)
#pragma unroll
            for (int q = 0; q < 4; q++) acc[i][j][q] = 0.f;

    const int mrow = m0 + lrow, mclamp = mrow < S_ ? mrow : S_ - 1;
    uint4 ra0, ra1, rb0, rb1;
    const bool loadB = (tid < 128);
    auto gload = [&](int c) {
        const int seg = c / 7;
        const int k0 = (c - seg * 7) * 32 + lcol;
        const __nv_bfloat16* A = (seg == 1) ? g_at_lo : g_at_hi;
        const __nv_bfloat16* ap = A + ((size_t)bh * S_ + mclamp) * SKP + k0;
        ra0 = *(const uint4*)ap; ra1 = *(const uint4*)(ap + 8);
        if (loadB) {
            const __nv_bfloat16* Bsrc = (seg == 2) ? g_vt_lo : g_vt_hi;
            const __nv_bfloat16* bp = Bsrc + ((size_t)bh * HD_ + n0 + lrow) * SKP + k0;
            rb0 = *(const uint4*)bp; rb1 = *(const uint4*)(bp + 8);
        }
    };
    auto sstore = [&](int st) {
        *(uint4*)&As[st][lrow][lcol] = ra0; *(uint4*)&As[st][lrow][lcol + 8] = ra1;
        if (loadB) {
            *(uint4*)&Bs[st][lrow][lcol] = rb0; *(uint4*)&Bs[st][lrow][lcol + 8] = rb1;
        }
    };

    const uint32_t aBase = smem_u32(&As[0][0][0]);
    const uint32_t bBase = smem_u32(&Bs[0][0][0]);
    const int arow = wm + (lane & 15);
    const int akoff = (lane >> 4) * 8;
    const int brow = wn + (lane & 7);
    const int bkoff = ((lane >> 3) & 1) * 8;

    gload(0); sstore(0);
    __syncthreads();
    for (int c = 0; c < 21; c++) {
        const int st = c & 1;
        if (c + 1 < 21) gload(c + 1);
        const uint32_t aS = aBase + st * (128 * SSTR * 2);
        const uint32_t bS = bBase + st * (64 * SSTR * 2);
#pragma unroll
        for (int ks = 0; ks < 2; ks++) {
            const int k = ks * 16;
            uint32_t af[2][4], bf[4][2];
#pragma unroll
            for (int mt = 0; mt < 2; mt++)
                ldsm_x4(af[mt], aS + ((arow + mt * 16) * SSTR + k + akoff) * 2);
#pragma unroll
            for (int nt = 0; nt < 4; nt++)
                ldsm_x2(bf[nt], bS + ((brow + nt * 8) * SSTR + k + bkoff) * 2);
#pragma unroll
            for (int mt = 0; mt < 2; mt++)
#pragma unroll
                for (int nt = 0; nt < 4; nt++)
                    mma16816(acc[mt][nt], af[mt], bf[nt]);
        }
        if (c + 1 < 21) sstore(st ^ 1);
        __syncthreads();
    }

    const int erow = lane >> 2, ecol = (lane & 3) * 2;
#pragma unroll
    for (int mt = 0; mt < 2; mt++) {
#pragma unroll
        for (int nt = 0; nt < 4; nt++) {
            const int col = n0 + wn + nt * 8 + ecol;   // < 192 always
            const int r0 = m0 + wm + mt * 16 + erow;
#pragma unroll
            for (int rr = 0; rr < 2; rr++) {
                const int r = r0 + rr * 8;
                if (r >= S_) continue;
                const float va = acc[mt][nt][rr * 2 + 0];
                const float vb = acc[mt][nt][rr * 2 + 1];
                __nv_bfloat16 h0, l0, h1, l1;
                split1(va, h0, l0); split1(vb, h1, l1);
                const size_t off = ((size_t)(b * S_ + r)) * E_ + h * HD_ + col;
                *(__nv_bfloat162*)&g_o_hi[off] = __nv_bfloat162(h0, h1);
                *(__nv_bfloat162*)&g_o_lo[off] = __nv_bfloat162(l0, l1);
            }
        }
    }
}

// ============================================================================
// Splits
// ============================================================================
__global__ __launch_bounds__(256) void weight_split(
    const float* __restrict__ w, __nv_bfloat16* __restrict__ hi,
    __nv_bfloat16* __restrict__ lo)
{
    const int gid = blockIdx.x * 256 + threadIdx.x;
    if (gid >= WN_ / 4) return;
    float4 v = *(const float4*)(w + gid * 4);
    __nv_bfloat16 h0, l0;
#pragma unroll
    for (int i = 0; i < 4; i++) {
        split1((&v.x)[i], h0, l0);
        hi[gid * 4 + i] = h0;
        lo[gid * 4 + i] = l0;
    }
}

__global__ __launch_bounds__(256) void patch_split(
    const float* __restrict__ x, __nv_bfloat16* __restrict__ hi,
    __nv_bfloat16* __restrict__ lo)
{
    const int gid = blockIdx.x * 256 + threadIdx.x;
    if (gid >= NE_ / 4) return;
    const int m = gid / 192;
    const int k = (gid - m * 192) * 4;
    const int b = m / S_;
    const int s = m - b * S_;
    const int gy = s / 14, gx = s - gy * 14;
    const int c = k >> 8;
    const int py = (k >> 4) & 15;
    const int px = k & 15;
    const float* src = x + ((((size_t)b * 3 + c) * 224 + gy * 16 + py) * 224 + gx * 16 + px);
    float4 v = *(const float4*)src;
    const size_t o = (size_t)m * E_ + k;
    __nv_bfloat16 h0, l0;
#pragma unroll
    for (int i = 0; i < 4; i++) {
        split1((&v.x)[i], h0, l0);
        hi[o + i] = h0;
        lo[o + i] = l0;
    }
}

// ============================================================================
// LayerNorm over [S,E] per batch
// ============================================================================
__global__ __launch_bounds__(256) void ln_partial(
    const float* __restrict__ A, const float* __restrict__ R)
{
    const int b = blockIdx.x, chunk = blockIdx.y;
    const size_t base = (size_t)b * LN_N + (size_t)chunk * LN_CH;
    float s = 0.f, sq = 0.f;
    for (int i = threadIdx.x; i < LN_CH; i += 256) {
        float v = A[base + i];
        if (R) v += R[base + i];
        s += v; sq += v * v;
    }
    __shared__ float ss[256], sb[256];
    ss[threadIdx.x] = s; sb[threadIdx.x] = sq;
    __syncthreads();
    for (int o = 128; o > 0; o >>= 1) {
        if (threadIdx.x < o) {
            ss[threadIdx.x] += ss[threadIdx.x + o];
            sb[threadIdx.x] += sb[threadIdx.x + o];
        }
        __syncthreads();
    }
    if (threadIdx.x == 0) {
        g_psum[b * LN_CHUNKS + chunk] = ss[0];
        g_psq [b * LN_CHUNKS + chunk] = sb[0];
    }
}

__global__ void ln_finalize()
{
    const int b = threadIdx.x;
    if (b >= B_) return;
    float s = 0.f, sq = 0.f;
#pragma unroll
    for (int i = 0; i < LN_CHUNKS; i++) {
        s  += g_psum[b * LN_CHUNKS + i];
        sq += g_psq [b * LN_CHUNKS + i];
    }
    const float inv_n = 1.0f / (float)LN_N;
    float mu = s * inv_n;
    float var = sq * inv_n - mu * mu;
    g_mu[b] = mu;
    g_rstd[b] = rsqrtf(var + 1e-5f);
}

__global__ __launch_bounds__(256) void ln_apply_split(
    const float* __restrict__ A, const float* __restrict__ w,
    const float* __restrict__ bias)
{
    const int gid = blockIdx.x * 256 + threadIdx.x;
    if (gid >= NE_) return;
    const int b = gid / LN_N;
    const int r = gid - b * LN_N;
    float v = (A[gid] - g_mu[b]) * g_rstd[b] * w[r] + bias[r];
    __nv_bfloat16 hi, lo;
    split1(v, hi, lo);
    g_h_hi[gid] = hi;
    g_h_lo[gid] = lo;
}

__global__ __launch_bounds__(256) void ln_apply(
    const float* __restrict__ A, const float* __restrict__ R,
    const float* __restrict__ w, const float* __restrict__ bias,
    float* __restrict__ out)
{
    const int gid = blockIdx.x * 256 + threadIdx.x;
    if (gid >= NE_) return;
    const int b = gid / LN_N;
    const int r = gid - b * LN_N;
    float v = A[gid] + R[gid];
    out[gid] = (v - g_mu[b]) * g_rstd[b] * w[r] + bias[r];
}

// ============================================================================
// Launch
// ============================================================================
extern "C" void kernel_launch(void* const* d_in, const int* in_sizes, int n_in,
                              void* d_out, int out_size)
{
    const float* x      = (const float*)d_in[0];
    const float* conv_w = (const float*)d_in[1];
    const float* conv_b = (const float*)d_in[2];
    const float* wq = (const float*)d_in[3];  const float* bq = (const float*)d_in[4];
    const float* wk = (const float*)d_in[5];  const float* bk = (const float*)d_in[6];
    const float* wv = (const float*)d_in[7];  const float* bv = (const float*)d_in[8];
    const float* wo = (const float*)d_in[9];  const float* bo = (const float*)d_in[10];
    const float* ln1w = (const float*)d_in[11]; const float* ln1b = (const float*)d_in[12];
    const float* ln2w = (const float*)d_in[13]; const float* ln2b = (const float*)d_in[14];
    float* out = (float*)d_out;

    float *emb, *op;
    cudaGetSymbolAddress((void**)&emb, g_emb);
    cudaGetSymbolAddress((void**)&op,  g_op);
    __nv_bfloat16 *aph, *apl, *hh, *hl, *qh, *ql, *kh, *kl, *vth, *vtl, *oh, *ol, *wh, *wl;
    cudaGetSymbolAddress((void**)&aph, g_ap_hi);
    cudaGetSymbolAddress((void**)&apl, g_ap_lo);
    cudaGetSymbolAddress((void**)&hh,  g_h_hi);
    cudaGetSymbolAddress((void**)&hl,  g_h_lo);
    cudaGetSymbolAddress((void**)&qh,  g_q_hi);
    cudaGetSymbolAddress((void**)&ql,  g_q_lo);
    cudaGetSymbolAddress((void**)&kh,  g_k_hi);
    cudaGetSymbolAddress((void**)&kl,  g_k_lo);
    cudaGetSymbolAddress((void**)&vth, g_vt_hi);
    cudaGetSymbolAddress((void**)&vtl, g_vt_lo);
    cudaGetSymbolAddress((void**)&oh,  g_o_hi);
    cudaGetSymbolAddress((void**)&ol,  g_o_lo);
    cudaGetSymbolAddress((void**)&wh,  g_w_hi);
    cudaGetSymbolAddress((void**)&wl,  g_w_lo);

    cudaFuncSetAttribute(gemm_mma, cudaFuncAttributeMaxDynamicSharedMemorySize, GEMM_SMEM);

    const dim3 gemm_grid(6, 49);
    const dim3 sc_grid(2, 2, NBH);         // 128x128 tiles
    const dim3 av_grid(3, 2, NBH);         // 64-col x 128-row tiles
    const dim3 lnp_grid(B_, LN_CHUNKS);
    const int  lna_blocks = NE_ / 256;
    const int  sm_blocks = (NBH * S_ * 32 + 255) / 256;
    const int  ws_blocks = (WN_ / 4 + 255) / 256;
    const int  ps_blocks = (NE_ / 4 + 255) / 256;
    const int  vz_blocks = (NBH * HD_ * (SKP - S_) + 255) / 256;

    // 0. splits
    weight_split<<<ws_blocks, 256>>>(conv_w, wh + 0 * (size_t)WN_, wl + 0 * (size_t)WN_);
    weight_split<<<ws_blocks, 256>>>(wq,     wh + 1 * (size_t)WN_, wl + 1 * (size_t)WN_);
    weight_split<<<ws_blocks, 256>>>(wk,     wh + 2 * (size_t)WN_, wl + 2 * (size_t)WN_);
    weight_split<<<ws_blocks, 256>>>(wv,     wh + 3 * (size_t)WN_, wl + 3 * (size_t)WN_);
    weight_split<<<ws_blocks, 256>>>(wo,     wh + 4 * (size_t)WN_, wl + 4 * (size_t)WN_);
    patch_split<<<ps_blocks, 256>>>(x, aph, apl);
    vt_zero<<<vz_blocks, 256>>>();
    // 1. patch embedding -> emb (fp32)
    gemm_mma<<<gemm_grid, 256, GEMM_SMEM>>>(
        aph, apl, wh + 0 * (size_t)WN_, wl + 0 * (size_t)WN_, conv_b, emb, nullptr, nullptr, 0);
    // 2. LN1 -> h hi/lo
    ln_partial<<<lnp_grid, 256>>>(emb, nullptr);
    ln_finalize<<<1, 64>>>();
    ln_apply_split<<<lna_blocks, 256>>>(emb, ln1w, ln1b);
    // 3. QKV
    gemm_mma<<<gemm_grid, 256, GEMM_SMEM>>>(
        hh, hl, wh + 1 * (size_t)WN_, wl + 1 * (size_t)WN_, bq, nullptr, qh, ql, 1);
    gemm_mma<<<gemm_grid, 256, GEMM_SMEM>>>(
        hh, hl, wh + 2 * (size_t)WN_, wl + 2 * (size_t)WN_, bk, nullptr, kh, kl, 1);
    gemm_mma<<<gemm_grid, 256, GEMM_SMEM>>>(
        hh, hl, wh + 3 * (size_t)WN_, wl + 3 * (size_t)WN_, bv, nullptr, vth, vtl, 2);
    // 4. attention
    scores_mma<<<sc_grid, 256>>>();
    softmax_rows<<<sm_blocks, 256>>>();
    av_mma<<<av_grid, 256>>>();
    // 5. output projection -> op (fp32)
    gemm_mma<<<gemm_grid, 256, GEMM_SMEM>>>(
        oh, ol, wh + 4 * (size_t)WN_, wl + 4 * (size_t)WN_, bo, op, nullptr, nullptr, 0);
    // 6. residual + LN2 -> out
    ln_partial<<<lnp_grid, 256>>>(emb, op);
    ln_finalize<<<1, 64>>>();
    ln_apply<<<lna_blocks, 256>>>(emb, op, ln2w, ln2b, out);
}

// round 7
// speedup vs baseline: 2.6602x; 1.1392x over previous
#include <cuda_runtime.h>
#include <cuda_bf16.h>
#include <math.h>
#include <stdint.h>

// Problem constants
#define B_   64
#define S_   196
#define E_   768
#define H_   4
#define HD_  192
#define M_   (B_*S_)        // 12544
#define NE_  (B_*S_*E_)     // 9,633,792
#define LN_N (S_*E_)        // 150,528
#define LN_CHUNKS 16
#define LN_CH (LN_N/LN_CHUNKS)   // 9408
#define WN_  (E_*E_)
#define SKP  224            // padded seq
#define NBH  (B_*H_)        // 256

// ---------------- scratch (device globals) ----------------
__device__ __align__(256) float g_emb[NE_];
__device__ __align__(256) float g_op[NE_];
__device__ __align__(256) float g_scores[NBH*S_*SKP];
__device__ float g_psum[B_*LN_CHUNKS];
__device__ float g_psq[B_*LN_CHUNKS];
__device__ float g_mu[B_];
__device__ float g_rstd[B_];

__device__ __align__(256) __nv_bfloat16 g_ap_hi[NE_];
__device__ __align__(256) __nv_bfloat16 g_ap_lo[NE_];
__device__ __align__(256) __nv_bfloat16 g_h_hi[NE_];
__device__ __align__(256) __nv_bfloat16 g_h_lo[NE_];
__device__ __align__(256) __nv_bfloat16 g_q_hi[NE_];
__device__ __align__(256) __nv_bfloat16 g_q_lo[NE_];
__device__ __align__(256) __nv_bfloat16 g_k_hi[NE_];
__device__ __align__(256) __nv_bfloat16 g_k_lo[NE_];
__device__ __align__(256) __nv_bfloat16 g_vt_hi[NBH*HD_*SKP];
__device__ __align__(256) __nv_bfloat16 g_vt_lo[NBH*HD_*SKP];
__device__ __align__(256) __nv_bfloat16 g_at_hi[NBH*S_*SKP];
__device__ __align__(256) __nv_bfloat16 g_at_lo[NBH*S_*SKP];
__device__ __align__(256) __nv_bfloat16 g_o_hi[NE_];
__device__ __align__(256) __nv_bfloat16 g_o_lo[NE_];
__device__ __align__(256) __nv_bfloat16 g_w_hi[5][WN_];
__device__ __align__(256) __nv_bfloat16 g_w_lo[5][WN_];

// ============================================================================
// PTX helpers
// ============================================================================
__device__ __forceinline__ uint32_t smem_u32(const void* p) {
    uint32_t a;
    asm("{ .reg .u64 t; cvta.to.shared.u64 t, %1; cvt.u32.u64 %0, t; }"
        : "=r"(a) : "l"(p));
    return a;
}
__device__ __forceinline__ void ldsm_x4(uint32_t* r, uint32_t addr) {
    asm volatile("ldmatrix.sync.aligned.m8n8.x4.shared.b16 {%0,%1,%2,%3}, [%4];"
                 : "=r"(r[0]), "=r"(r[1]), "=r"(r[2]), "=r"(r[3]) : "r"(addr));
}
__device__ __forceinline__ void ldsm_x2(uint32_t* r, uint32_t addr) {
    asm volatile("ldmatrix.sync.aligned.m8n8.x2.shared.b16 {%0,%1}, [%2];"
                 : "=r"(r[0]), "=r"(r[1]) : "r"(addr));
}
__device__ __forceinline__ void mma16816(float* c, const uint32_t* a, const uint32_t* b) {
    asm volatile(
        "mma.sync.aligned.m16n8k16.row.col.f32.bf16.bf16.f32 "
        "{%0,%1,%2,%3}, {%4,%5,%6,%7}, {%8,%9}, {%0,%1,%2,%3};"
        : "+f"(c[0]), "+f"(c[1]), "+f"(c[2]), "+f"(c[3])
        : "r"(a[0]), "r"(a[1]), "r"(a[2]), "r"(a[3]), "r"(b[0]), "r"(b[1]));
}
__device__ __forceinline__ void cp16(uint32_t saddr, const void* gaddr) {
    asm volatile("cp.async.cg.shared.global [%0], [%1], 16;"
                 :: "r"(saddr), "l"(gaddr) : "memory");
}
#define CP_COMMIT() asm volatile("cp.async.commit_group;" ::: "memory")
#define CP_WAIT1()  asm volatile("cp.async.wait_group 1;" ::: "memory")
#define CP_WAIT0()  asm volatile("cp.async.wait_group 0;" ::: "memory")

__device__ __forceinline__ void split1(float x, __nv_bfloat16& hi, __nv_bfloat16& lo) {
    hi = __float2bfloat16(x);
    lo = __float2bfloat16(x - __bfloat162float(hi));
}

// ============================================================================
// HMMA bf16-split GEMM — shared-operand restructure.
// Per K-chunk (64): load Ahi/Alo/Bhi/Blo once, do 3 term MMA blocks:
//   hi*hi, lo*hi (reuse Bhi frags), hi*lo (reuse Ahi frags).
// CTA 256x128, 12 chunks, 2-stage cp.async. 8 warps, warp tile 64x64.
// mode 0: fp32 C.  mode 1: split hi/lo.  mode 2: split + per-head transpose (V).
// ============================================================================
#define ASTR 72
#define ROWB 144
#define A_SZ (256 * ROWB)            // 36864
#define B_SZ (128 * ROWB)            // 18432
#define STG_BYTES (2*A_SZ + 2*B_SZ)  // 110592
#define GEMM_SMEM (2 * STG_BYTES)    // 221184

__global__ __launch_bounds__(256, 1) void gemm_mma(
    const __nv_bfloat16* __restrict__ Ahi, const __nv_bfloat16* __restrict__ Alo,
    const __nv_bfloat16* __restrict__ Bhi, const __nv_bfloat16* __restrict__ Blo,
    const float* __restrict__ bias, float* __restrict__ C,
    __nv_bfloat16* __restrict__ Chi, __nv_bfloat16* __restrict__ Clo, int mode)
{
    extern __shared__ char smem[];
    const uint32_t sbase = smem_u32(smem);
    const int tid = threadIdx.x;
    const int wid = tid >> 5, lane = tid & 31;
    const int m0 = blockIdx.y * 256, n0 = blockIdx.x * 128;
    const int wm = (wid >> 1) * 64, wn = (wid & 1) * 64;
    const int lr = tid >> 3, lseg = tid & 7;

    float acc[4][8][4];
#pragma unroll
    for (int i = 0; i < 4; i++)
#pragma unroll
        for (int j = 0; j < 8; j++)
#pragma unroll
            for (int q = 0; q < 4; q++) acc[i][j][q] = 0.f;

    auto issue = [&](int c, int st) {
        const int k0 = c * 64 + lseg * 8;
        const uint32_t base = sbase + st * STG_BYTES;
#pragma unroll
        for (int i = 0; i < 8; i++) {
            const int row = i * 32 + lr;
            const size_t go = (size_t)(m0 + row) * E_ + k0;
            const uint32_t so = row * ROWB + lseg * 16;
            cp16(base + so, Ahi + go);
            cp16(base + A_SZ + so, Alo + go);
        }
#pragma unroll
        for (int i = 0; i < 4; i++) {
            const int row = i * 32 + lr;
            const size_t go = (size_t)(n0 + row) * E_ + k0;
            const uint32_t so = row * ROWB + lseg * 16;
            cp16(base + 2*A_SZ + so, Bhi + go);
            cp16(base + 2*A_SZ + B_SZ + so, Blo + go);
        }
    };

    const int arow = wm + (lane & 15);
    const int akoff = (lane >> 4) * 8;
    const int brow = wn + (lane & 7) + ((lane >> 4) << 3);
    const int bkoff = ((lane >> 3) & 1) * 8;

    issue(0, 0); CP_COMMIT();

    for (int c = 0; c < 12; c++) {
        const int st = c & 1;
        if (c + 1 < 12) { issue(c + 1, st ^ 1); CP_COMMIT(); CP_WAIT1(); }
        else CP_WAIT0();
        __syncthreads();
        const uint32_t aHi = sbase + st * STG_BYTES;
        const uint32_t aLo = aHi + A_SZ;
        const uint32_t bHi = aHi + 2*A_SZ;
        const uint32_t bLo = bHi + B_SZ;
#pragma unroll
        for (int ks = 0; ks < 4; ks++) {
            const int k = ks * 16;
            uint32_t afh[4][4], bfh[4][4];
#pragma unroll
            for (int mt = 0; mt < 4; mt++)
                ldsm_x4(afh[mt], aHi + ((arow + mt * 16) * ASTR + k + akoff) * 2);
#pragma unroll
            for (int nt2 = 0; nt2 < 4; nt2++)
                ldsm_x4(bfh[nt2], bHi + ((brow + nt2 * 16) * ASTR + k + bkoff) * 2);
            // term hi*hi
#pragma unroll
            for (int mt = 0; mt < 4; mt++)
#pragma unroll
                for (int nt = 0; nt < 8; nt++)
                    mma16816(acc[mt][nt], afh[mt], &bfh[nt >> 1][(nt & 1) * 2]);
            // term lo*hi (reuse bfh)
            {
                uint32_t afl[4][4];
#pragma unroll
                for (int mt = 0; mt < 4; mt++)
                    ldsm_x4(afl[mt], aLo + ((arow + mt * 16) * ASTR + k + akoff) * 2);
#pragma unroll
                for (int mt = 0; mt < 4; mt++)
#pragma unroll
                    for (int nt = 0; nt < 8; nt++)
                        mma16816(acc[mt][nt], afl[mt], &bfh[nt >> 1][(nt & 1) * 2]);
            }
            // term hi*lo (reuse afh)
            {
                uint32_t bfl[4][4];
#pragma unroll
                for (int nt2 = 0; nt2 < 4; nt2++)
                    ldsm_x4(bfl[nt2], bLo + ((brow + nt2 * 16) * ASTR + k + bkoff) * 2);
#pragma unroll
                for (int mt = 0; mt < 4; mt++)
#pragma unroll
                    for (int nt = 0; nt < 8; nt++)
                        mma16816(acc[mt][nt], afh[mt], &bfl[nt >> 1][(nt & 1) * 2]);
            }
        }
        __syncthreads();
    }

    const int erow = lane >> 2;
    const int ecol = (lane & 3) * 2;
#pragma unroll
    for (int mt = 0; mt < 4; mt++) {
#pragma unroll
        for (int nt = 0; nt < 8; nt++) {
            const int col = n0 + wn + nt * 8 + ecol;
            const float b0 = bias[col], b1 = bias[col + 1];
            const int r0 = m0 + wm + mt * 16 + erow;
            float v00 = acc[mt][nt][0] + b0, v01 = acc[mt][nt][1] + b1;
            float v10 = acc[mt][nt][2] + b0, v11 = acc[mt][nt][3] + b1;
            if (mode == 0) {
                *(float2*)&C[(size_t)r0 * E_ + col] = make_float2(v00, v01);
                *(float2*)&C[(size_t)(r0 + 8) * E_ + col] = make_float2(v10, v11);
            } else if (mode == 1) {
                __nv_bfloat16 h0, l0, h1, l1;
                split1(v00, h0, l0); split1(v01, h1, l1);
                size_t off = (size_t)r0 * E_ + col;
                *(__nv_bfloat162*)&Chi[off] = __nv_bfloat162(h0, h1);
                *(__nv_bfloat162*)&Clo[off] = __nv_bfloat162(l0, l1);
                split1(v10, h0, l0); split1(v11, h1, l1);
                off = (size_t)(r0 + 8) * E_ + col;
                *(__nv_bfloat162*)&Chi[off] = __nv_bfloat162(h0, h1);
                *(__nv_bfloat162*)&Clo[off] = __nv_bfloat162(l0, l1);
            } else {
                const int hh = col / HD_, d = col - hh * HD_;
#pragma unroll
                for (int rr = 0; rr < 2; rr++) {
                    const int r = r0 + rr * 8;
                    const int bb = r / S_, s = r - bb * S_;
                    const float va = rr ? v10 : v00;
                    const float vb = rr ? v11 : v01;
                    __nv_bfloat16 h0, l0;
                    size_t o0 = ((size_t)(bb * H_ + hh) * HD_ + d) * SKP + s;
                    split1(va, h0, l0); Chi[o0] = h0; Clo[o0] = l0;
                    split1(vb, h0, l0); Chi[o0 + SKP] = h0; Clo[o0 + SKP] = l0;
                }
            }
        }
    }
}

// ============================================================================
// Attention scores via HMMA: 256 threads, CTA tile 128x128, warp tile 64x32.
// ============================================================================
#define SSTR 40

__global__ __launch_bounds__(256) void scores_mma()
{
    __shared__ __nv_bfloat16 As[2][128][SSTR];
    __shared__ __nv_bfloat16 Bs[2][128][SSTR];
    const int bh = blockIdx.z;
    const int b = bh >> 2, h = bh & 3;
    const int tid = threadIdx.x;
    const int wid = tid >> 5, lane = tid & 31;
    const int m0 = blockIdx.y * 128, n0 = blockIdx.x * 128;
    const int wm = (wid >> 2) * 64, wn = (wid & 3) * 32;
    const int lrow = tid >> 1, lcol = (tid & 1) * 16;

    float acc[4][4][4];
#pragma unroll
    for (int i = 0; i < 4; i++)
#pragma unroll
        for (int j = 0; j < 4; j++)
#pragma unroll
            for (int q = 0; q < 4; q++) acc[i][j][q] = 0.f;

    const int mrow = m0 + lrow, mclamp = mrow < S_ ? mrow : S_ - 1;
    const int nrow = n0 + lrow, nclamp = nrow < S_ ? nrow : S_ - 1;
    uint4 ra0, ra1, rb0, rb1;
    auto gload = [&](int c) {
        const int seg = c / 6;
        const int k0 = (c - seg * 6) * 32 + lcol;
        const __nv_bfloat16* A = (seg == 1) ? g_q_lo : g_q_hi;
        const __nv_bfloat16* B = (seg == 2) ? g_k_lo : g_k_hi;
        const __nv_bfloat16* ap = A + (size_t)(b * S_ + mclamp) * E_ + h * HD_ + k0;
        const __nv_bfloat16* bp = B + (size_t)(b * S_ + nclamp) * E_ + h * HD_ + k0;
        ra0 = *(const uint4*)ap; ra1 = *(const uint4*)(ap + 8);
        rb0 = *(const uint4*)bp; rb1 = *(const uint4*)(bp + 8);
    };
    auto sstore = [&](int st) {
        *(uint4*)&As[st][lrow][lcol] = ra0; *(uint4*)&As[st][lrow][lcol + 8] = ra1;
        *(uint4*)&Bs[st][lrow][lcol] = rb0; *(uint4*)&Bs[st][lrow][lcol + 8] = rb1;
    };

    const uint32_t aBase = smem_u32(&As[0][0][0]);
    const uint32_t bBase = smem_u32(&Bs[0][0][0]);
    const int arow = wm + (lane & 15);
    const int akoff = (lane >> 4) * 8;
    const int brow = wn + (lane & 7);
    const int bkoff = ((lane >> 3) & 1) * 8;

    gload(0); sstore(0);
    __syncthreads();
    for (int c = 0; c < 18; c++) {
        const int st = c & 1;
        if (c + 1 < 18) gload(c + 1);
        const uint32_t aS = aBase + st * (128 * SSTR * 2);
        const uint32_t bS = bBase + st * (128 * SSTR * 2);
#pragma unroll
        for (int ks = 0; ks < 2; ks++) {
            const int k = ks * 16;
            uint32_t af[4][4], bf[4][2];
#pragma unroll
            for (int mt = 0; mt < 4; mt++)
                ldsm_x4(af[mt], aS + ((arow + mt * 16) * SSTR + k + akoff) * 2);
#pragma unroll
            for (int nt = 0; nt < 4; nt++)
                ldsm_x2(bf[nt], bS + ((brow + nt * 8) * SSTR + k + bkoff) * 2);
#pragma unroll
            for (int mt = 0; mt < 4; mt++)
#pragma unroll
                for (int nt = 0; nt < 4; nt++)
                    mma16816(acc[mt][nt], af[mt], bf[nt]);
        }
        if (c + 1 < 18) sstore(st ^ 1);
        __syncthreads();
    }

    const float scale = rsqrtf((float)HD_);
    const int erow = lane >> 2, ecol = (lane & 3) * 2;
    float* Sp = g_scores + (size_t)bh * S_ * SKP;
#pragma unroll
    for (int mt = 0; mt < 4; mt++) {
#pragma unroll
        for (int nt = 0; nt < 4; nt++) {
            const int col = n0 + wn + nt * 8 + ecol;
            if (col >= S_) continue;
            const int r0 = m0 + wm + mt * 16 + erow;
            if (r0 < S_)
                *(float2*)&Sp[(size_t)r0 * SKP + col] =
                    make_float2(acc[mt][nt][0] * scale, acc[mt][nt][1] * scale);
            if (r0 + 8 < S_)
                *(float2*)&Sp[(size_t)(r0 + 8) * SKP + col] =
                    make_float2(acc[mt][nt][2] * scale, acc[mt][nt][3] * scale);
        }
    }
}

// ============================================================================
// Softmax rows -> bf16 hi/lo probs
// ============================================================================
__global__ __launch_bounds__(256) void softmax_rows()
{
    const int row = (blockIdx.x * blockDim.x + threadIdx.x) >> 5;
    const int lane = threadIdx.x & 31;
    if (row >= NBH * S_) return;
    const float* p = g_scores + (size_t)row * SKP;
    float v[7];
    float mx = -1e30f;
#pragma unroll
    for (int i = 0; i < 7; i++) {
        int j = lane + i * 32;
        v[i] = (j < S_) ? p[j] : -1e30f;
        mx = fmaxf(mx, v[i]);
    }
#pragma unroll
    for (int o = 16; o > 0; o >>= 1) mx = fmaxf(mx, __shfl_xor_sync(0xFFFFFFFFu, mx, o));
    float sum = 0.f;
#pragma unroll
    for (int i = 0; i < 7; i++) {
        int j = lane + i * 32;
        v[i] = (j < S_) ? __expf(v[i] - mx) : 0.f;
        sum += v[i];
    }
#pragma unroll
    for (int o = 16; o > 0; o >>= 1) sum += __shfl_xor_sync(0xFFFFFFFFu, sum, o);
    const float inv = 1.0f / sum;
    __nv_bfloat16* ah = g_at_hi + (size_t)row * SKP;
    __nv_bfloat16* al = g_at_lo + (size_t)row * SKP;
#pragma unroll
    for (int i = 0; i < 7; i++) {
        int j = lane + i * 32;
        float val = (j < S_) ? v[i] * inv : 0.f;
        __nv_bfloat16 hi, lo;
        split1(val, hi, lo);
        ah[j] = hi; al[j] = lo;
    }
}

__global__ __launch_bounds__(256) void vt_zero()
{
    const int gid = blockIdx.x * 256 + threadIdx.x;
    const int total = NBH * HD_ * (SKP - S_);
    if (gid >= total) return;
    const int row = gid / (SKP - S_);
    const int s = S_ + gid - row * (SKP - S_);
    g_vt_hi[(size_t)row * SKP + s] = __float2bfloat16(0.f);
    g_vt_lo[(size_t)row * SKP + s] = __float2bfloat16(0.f);
}

// ============================================================================
// AV via HMMA: 256 threads, CTA tile 128x64, warp tile 32x32.
// ============================================================================
__global__ __launch_bounds__(256) void av_mma()
{
    __shared__ __nv_bfloat16 As[2][128][SSTR];
    __shared__ __nv_bfloat16 Bs[2][64][SSTR];
    const int bh = blockIdx.z;
    const int b = bh >> 2, h = bh & 3;
    const int tid = threadIdx.x;
    const int wid = tid >> 5, lane = tid & 31;
    const int m0 = blockIdx.y * 128, n0 = blockIdx.x * 64;
    const int wm = (wid >> 1) * 32, wn = (wid & 1) * 32;
    const int lrow = tid >> 1, lcol = (tid & 1) * 16;

    float acc[2][4][4];
#pragma unroll
    for (int i = 0; i < 2; i++)
#pragma unroll
        for (int j = 0; j < 4; j++)
#pragma unroll
            for (int q = 0; q < 4; q++) acc[i][j][q] = 0.f;

    const int mrow = m0 + lrow, mclamp = mrow < S_ ? mrow : S_ - 1;
    uint4 ra0, ra1, rb0, rb1;
    const bool loadB = (tid < 128);
    auto gload = [&](int c) {
        const int seg = c / 7;
        const int k0 = (c - seg * 7) * 32 + lcol;
        const __nv_bfloat16* A = (seg == 1) ? g_at_lo : g_at_hi;
        const __nv_bfloat16* ap = A + ((size_t)bh * S_ + mclamp) * SKP + k0;
        ra0 = *(const uint4*)ap; ra1 = *(const uint4*)(ap + 8);
        if (loadB) {
            const __nv_bfloat16* Bsrc = (seg == 2) ? g_vt_lo : g_vt_hi;
            const __nv_bfloat16* bp = Bsrc + ((size_t)bh * HD_ + n0 + lrow) * SKP + k0;
            rb0 = *(const uint4*)bp; rb1 = *(const uint4*)(bp + 8);
        }
    };
    auto sstore = [&](int st) {
        *(uint4*)&As[st][lrow][lcol] = ra0; *(uint4*)&As[st][lrow][lcol + 8] = ra1;
        if (loadB) {
            *(uint4*)&Bs[st][lrow][lcol] = rb0; *(uint4*)&Bs[st][lrow][lcol + 8] = rb1;
        }
    };

    const uint32_t aBase = smem_u32(&As[0][0][0]);
    const uint32_t bBase = smem_u32(&Bs[0][0][0]);
    const int arow = wm + (lane & 15);
    const int akoff = (lane >> 4) * 8;
    const int brow = wn + (lane & 7);
    const int bkoff = ((lane >> 3) & 1) * 8;

    gload(0); sstore(0);
    __syncthreads();
    for (int c = 0; c < 21; c++) {
        const int st = c & 1;
        if (c + 1 < 21) gload(c + 1);
        const uint32_t aS = aBase + st * (128 * SSTR * 2);
        const uint32_t bS = bBase + st * (64 * SSTR * 2);
#pragma unroll
        for (int ks = 0; ks < 2; ks++) {
            const int k = ks * 16;
            uint32_t af[2][4], bf[4][2];
#pragma unroll
            for (int mt = 0; mt < 2; mt++)
                ldsm_x4(af[mt], aS + ((arow + mt * 16) * SSTR + k + akoff) * 2);
#pragma unroll
            for (int nt = 0; nt < 4; nt++)
                ldsm_x2(bf[nt], bS + ((brow + nt * 8) * SSTR + k + bkoff) * 2);
#pragma unroll
            for (int mt = 0; mt < 2; mt++)
#pragma unroll
                for (int nt = 0; nt < 4; nt++)
                    mma16816(acc[mt][nt], af[mt], bf[nt]);
        }
        if (c + 1 < 21) sstore(st ^ 1);
        __syncthreads();
    }

    const int erow = lane >> 2, ecol = (lane & 3) * 2;
#pragma unroll
    for (int mt = 0; mt < 2; mt++) {
#pragma unroll
        for (int nt = 0; nt < 4; nt++) {
            const int col = n0 + wn + nt * 8 + ecol;
            const int r0 = m0 + wm + mt * 16 + erow;
#pragma unroll
            for (int rr = 0; rr < 2; rr++) {
                const int r = r0 + rr * 8;
                if (r >= S_) continue;
                const float va = acc[mt][nt][rr * 2 + 0];
                const float vb = acc[mt][nt][rr * 2 + 1];
                __nv_bfloat16 h0, l0, h1, l1;
                split1(va, h0, l0); split1(vb, h1, l1);
                const size_t off = ((size_t)(b * S_ + r)) * E_ + h * HD_ + col;
                *(__nv_bfloat162*)&g_o_hi[off] = __nv_bfloat162(h0, h1);
                *(__nv_bfloat162*)&g_o_lo[off] = __nv_bfloat162(l0, l1);
            }
        }
    }
}

// ============================================================================
// Splits
// ============================================================================
__global__ __launch_bounds__(256) void weight_split(
    const float* __restrict__ w, __nv_bfloat16* __restrict__ hi,
    __nv_bfloat16* __restrict__ lo)
{
    const int gid = blockIdx.x * 256 + threadIdx.x;
    if (gid >= WN_ / 4) return;
    float4 v = *(const float4*)(w + gid * 4);
    __nv_bfloat16 h[4], l[4];
#pragma unroll
    for (int i = 0; i < 4; i++) split1((&v.x)[i], h[i], l[i]);
    *(__nv_bfloat162*)&hi[gid * 4]     = __nv_bfloat162(h[0], h[1]);
    *(__nv_bfloat162*)&hi[gid * 4 + 2] = __nv_bfloat162(h[2], h[3]);
    *(__nv_bfloat162*)&lo[gid * 4]     = __nv_bfloat162(l[0], l[1]);
    *(__nv_bfloat162*)&lo[gid * 4 + 2] = __nv_bfloat162(l[2], l[3]);
}

__global__ __launch_bounds__(256) void patch_split(
    const float* __restrict__ x, __nv_bfloat16* __restrict__ hi,
    __nv_bfloat16* __restrict__ lo)
{
    const int gid = blockIdx.x * 256 + threadIdx.x;
    if (gid >= NE_ / 4) return;
    const int m = gid / 192;
    const int k = (gid - m * 192) * 4;
    const int b = m / S_;
    const int s = m - b * S_;
    const int gy = s / 14, gx = s - gy * 14;
    const int c = k >> 8;
    const int py = (k >> 4) & 15;
    const int px = k & 15;
    const float* src = x + ((((size_t)b * 3 + c) * 224 + gy * 16 + py) * 224 + gx * 16 + px);
    float4 v = *(const float4*)src;
    const size_t o = (size_t)m * E_ + k;
    __nv_bfloat16 h[4], l[4];
#pragma unroll
    for (int i = 0; i < 4; i++) split1((&v.x)[i], h[i], l[i]);
    *(__nv_bfloat162*)&hi[o]     = __nv_bfloat162(h[0], h[1]);
    *(__nv_bfloat162*)&hi[o + 2] = __nv_bfloat162(h[2], h[3]);
    *(__nv_bfloat162*)&lo[o]     = __nv_bfloat162(l[0], l[1]);
    *(__nv_bfloat162*)&lo[o + 2] = __nv_bfloat162(l[2], l[3]);
}

// ============================================================================
// LayerNorm over [S,E] per batch — float4 vectorized
// ============================================================================
__global__ __launch_bounds__(256) void ln_partial(
    const float* __restrict__ A, const float* __restrict__ R)
{
    const int b = blockIdx.x, chunk = blockIdx.y;
    const size_t base4 = ((size_t)b * LN_N + (size_t)chunk * LN_CH) / 4;
    const float4* A4 = (const float4*)A;
    const float4* R4 = (const float4*)R;
    float s = 0.f, sq = 0.f;
    for (int i = threadIdx.x; i < LN_CH / 4; i += 256) {
        float4 v = A4[base4 + i];
        if (R) {
            float4 r = R4[base4 + i];
            v.x += r.x; v.y += r.y; v.z += r.z; v.w += r.w;
        }
        s += v.x + v.y + v.z + v.w;
        sq += v.x * v.x + v.y * v.y + v.z * v.z + v.w * v.w;
    }
    __shared__ float ss[256], sb[256];
    ss[threadIdx.x] = s; sb[threadIdx.x] = sq;
    __syncthreads();
    for (int o = 128; o > 0; o >>= 1) {
        if (threadIdx.x < o) {
            ss[threadIdx.x] += ss[threadIdx.x + o];
            sb[threadIdx.x] += sb[threadIdx.x + o];
        }
        __syncthreads();
    }
    if (threadIdx.x == 0) {
        g_psum[b * LN_CHUNKS + chunk] = ss[0];
        g_psq [b * LN_CHUNKS + chunk] = sb[0];
    }
}

__global__ void ln_finalize()
{
    const int b = threadIdx.x;
    if (b >= B_) return;
    float s = 0.f, sq = 0.f;
#pragma unroll
    for (int i = 0; i < LN_CHUNKS; i++) {
        s  += g_psum[b * LN_CHUNKS + i];
        sq += g_psq [b * LN_CHUNKS + i];
    }
    const float inv_n = 1.0f / (float)LN_N;
    float mu = s * inv_n;
    float var = sq * inv_n - mu * mu;
    g_mu[b] = mu;
    g_rstd[b] = rsqrtf(var + 1e-5f);
}

__global__ __launch_bounds__(256) void ln_apply_split(
    const float* __restrict__ A, const float* __restrict__ w,
    const float* __restrict__ bias)
{
    const int gid = blockIdx.x * 256 + threadIdx.x;     // float4 index
    if (gid >= NE_ / 4) return;
    const int b = gid / (LN_N / 4);
    const int r4 = gid - b * (LN_N / 4);
    const float mu = g_mu[b], rs = g_rstd[b];
    float4 v = ((const float4*)A)[gid];
    float4 ww = ((const float4*)w)[r4];
    float4 bb = ((const float4*)bias)[r4];
    float o0 = (v.x - mu) * rs * ww.x + bb.x;
    float o1 = (v.y - mu) * rs * ww.y + bb.y;
    float o2 = (v.z - mu) * rs * ww.z + bb.z;
    float o3 = (v.w - mu) * rs * ww.w + bb.w;
    __nv_bfloat16 h[4], l[4];
    split1(o0, h[0], l[0]); split1(o1, h[1], l[1]);
    split1(o2, h[2], l[2]); split1(o3, h[3], l[3]);
    const size_t o = (size_t)gid * 4;
    *(__nv_bfloat162*)&g_h_hi[o]     = __nv_bfloat162(h[0], h[1]);
    *(__nv_bfloat162*)&g_h_hi[o + 2] = __nv_bfloat162(h[2], h[3]);
    *(__nv_bfloat162*)&g_h_lo[o]     = __nv_bfloat162(l[0], l[1]);
    *(__nv_bfloat162*)&g_h_lo[o + 2] = __nv_bfloat162(l[2], l[3]);
}

__global__ __launch_bounds__(256) void ln_apply(
    const float* __restrict__ A, const float* __restrict__ R,
    const float* __restrict__ w, const float* __restrict__ bias,
    float* __restrict__ out)
{
    const int gid = blockIdx.x * 256 + threadIdx.x;     // float4 index
    if (gid >= NE_ / 4) return;
    const int b = gid / (LN_N / 4);
    const int r4 = gid - b * (LN_N / 4);
    const float mu = g_mu[b], rs = g_rstd[b];
    float4 v = ((const float4*)A)[gid];
    float4 r = ((const float4*)R)[gid];
    v.x += r.x; v.y += r.y; v.z += r.z; v.w += r.w;
    float4 ww = ((const float4*)w)[r4];
    float4 bb = ((const float4*)bias)[r4];
    float4 o;
    o.x = (v.x - mu) * rs * ww.x + bb.x;
    o.y = (v.y - mu) * rs * ww.y + bb.y;
    o.z = (v.z - mu) * rs * ww.z + bb.z;
    o.w = (v.w - mu) * rs * ww.w + bb.w;
    ((float4*)out)[gid] = o;
}

// ============================================================================
// Launch
// ============================================================================
extern "C" void kernel_launch(void* const* d_in, const int* in_sizes, int n_in,
                              void* d_out, int out_size)
{
    const float* x      = (const float*)d_in[0];
    const float* conv_w = (const float*)d_in[1];
    const float* conv_b = (const float*)d_in[2];
    const float* wq = (const float*)d_in[3];  const float* bq = (const float*)d_in[4];
    const float* wk = (const float*)d_in[5];  const float* bk = (const float*)d_in[6];
    const float* wv = (const float*)d_in[7];  const float* bv = (const float*)d_in[8];
    const float* wo = (const float*)d_in[9];  const float* bo = (const float*)d_in[10];
    const float* ln1w = (const float*)d_in[11]; const float* ln1b = (const float*)d_in[12];
    const float* ln2w = (const float*)d_in[13]; const float* ln2b = (const float*)d_in[14];
    float* out = (float*)d_out;

    float *emb, *op;
    cudaGetSymbolAddress((void**)&emb, g_emb);
    cudaGetSymbolAddress((void**)&op,  g_op);
    __nv_bfloat16 *aph, *apl, *hh, *hl, *qh, *ql, *kh, *kl, *vth, *vtl, *oh, *ol, *wh, *wl;
    cudaGetSymbolAddress((void**)&aph, g_ap_hi);
    cudaGetSymbolAddress((void**)&apl, g_ap_lo);
    cudaGetSymbolAddress((void**)&hh,  g_h_hi);
    cudaGetSymbolAddress((void**)&hl,  g_h_lo);
    cudaGetSymbolAddress((void**)&qh,  g_q_hi);
    cudaGetSymbolAddress((void**)&ql,  g_q_lo);
    cudaGetSymbolAddress((void**)&kh,  g_k_hi);
    cudaGetSymbolAddress((void**)&kl,  g_k_lo);
    cudaGetSymbolAddress((void**)&vth, g_vt_hi);
    cudaGetSymbolAddress((void**)&vtl, g_vt_lo);
    cudaGetSymbolAddress((void**)&oh,  g_o_hi);
    cudaGetSymbolAddress((void**)&ol,  g_o_lo);
    cudaGetSymbolAddress((void**)&wh,  g_w_hi);
    cudaGetSymbolAddress((void**)&wl,  g_w_lo);

    cudaFuncSetAttribute(gemm_mma, cudaFuncAttributeMaxDynamicSharedMemorySize, GEMM_SMEM);

    const dim3 gemm_grid(6, 49);
    const dim3 sc_grid(2, 2, NBH);
    const dim3 av_grid(3, 2, NBH);
    const dim3 lnp_grid(B_, LN_CHUNKS);
    const int  lna_blocks = (NE_ / 4) / 256;
    const int  sm_blocks = (NBH * S_ * 32 + 255) / 256;
    const int  ws_blocks = (WN_ / 4 + 255) / 256;
    const int  ps_blocks = (NE_ / 4 + 255) / 256;
    const int  vz_blocks = (NBH * HD_ * (SKP - S_) + 255) / 256;

    // 0. splits
    weight_split<<<ws_blocks, 256>>>(conv_w, wh + 0 * (size_t)WN_, wl + 0 * (size_t)WN_);
    weight_split<<<ws_blocks, 256>>>(wq,     wh + 1 * (size_t)WN_, wl + 1 * (size_t)WN_);
    weight_split<<<ws_blocks, 256>>>(wk,     wh + 2 * (size_t)WN_, wl + 2 * (size_t)WN_);
    weight_split<<<ws_blocks, 256>>>(wv,     wh + 3 * (size_t)WN_, wl + 3 * (size_t)WN_);
    weight_split<<<ws_blocks, 256>>>(wo,     wh + 4 * (size_t)WN_, wl + 4 * (size_t)WN_);
    patch_split<<<ps_blocks, 256>>>(x, aph, apl);
    vt_zero<<<vz_blocks, 256>>>();
    // 1. patch embedding -> emb (fp32)
    gemm_mma<<<gemm_grid, 256, GEMM_SMEM>>>(
        aph, apl, wh + 0 * (size_t)WN_, wl + 0 * (size_t)WN_, conv_b, emb, nullptr, nullptr, 0);
    // 2. LN1 -> h hi/lo
    ln_partial<<<lnp_grid, 256>>>(emb, nullptr);
    ln_finalize<<<1, 64>>>();
    ln_apply_split<<<lna_blocks, 256>>>(emb, ln1w, ln1b);
    // 3. QKV
    gemm_mma<<<gemm_grid, 256, GEMM_SMEM>>>(
        hh, hl, wh + 1 * (size_t)WN_, wl + 1 * (size_t)WN_, bq, nullptr, qh, ql, 1);
    gemm_mma<<<gemm_grid, 256, GEMM_SMEM>>>(
        hh, hl, wh + 2 * (size_t)WN_, wl + 2 * (size_t)WN_, bk, nullptr, kh, kl, 1);
    gemm_mma<<<gemm_grid, 256, GEMM_SMEM>>>(
        hh, hl, wh + 3 * (size_t)WN_, wl + 3 * (size_t)WN_, bv, nullptr, vth, vtl, 2);
    // 4. attention
    scores_mma<<<sc_grid, 256>>>();
    softmax_rows<<<sm_blocks, 256>>>();
    av_mma<<<av_grid, 256>>>();
    // 5. output projection -> op (fp32)
    gemm_mma<<<gemm_grid, 256, GEMM_SMEM>>>(
        oh, ol, wh + 4 * (size_t)WN_, wl + 4 * (size_t)WN_, bo, op, nullptr, nullptr, 0);
    // 6. residual + LN2 -> out
    ln_partial<<<lnp_grid, 256>>>(emb, op);
    ln_finalize<<<1, 64>>>();
    ln_apply<<<lna_blocks, 256>>>(emb, op, ln2w, ln2b, out);
}